// round 12
// baseline (speedup 1.0000x reference)
#include <cuda_runtime.h>
#include <cuda_bf16.h>
#include <math.h>
#include <stdint.h>

#define HID    768
#define SEQ    512
#define BATCH  8
#define NHEAD  12
#define DHEAD  64
#define FFD    3072
#define NLAYER 12
#define NTOK   4096   // BATCH*SEQ

// weight split buffer layout (element offsets into g_wh/g_wl)
#define WSZ_QKVO 589824            // 768*768
#define WSZ_FF   2359296           // 768*3072
#define OFF_WQ   0
#define OFF_WK   7077888
#define OFF_WV   14155776
#define OFF_WO   21233664
#define OFF_W1   28311552
#define OFF_W2   56623104
#define WTOT     84934656

// ---------------- scratch (device globals; no allocation allowed) ----------------
__device__ float g_h[NTOK * HID];          // fp32 residual stream
__device__ float g_t[NTOK * HID];          // split-K partial 0 + bias + res
__device__ float g_t2[NTOK * HID];         // split-K partial 1
__device__ float g_t3[NTOK * HID];         // split-K partial 2
__device__ __nv_bfloat16 g_ahi[NTOK * HID], g_alo[NTOK * HID];     // LN out split
__device__ __nv_bfloat16 g_qkvh[3 * NTOK * HID], g_qkvl[3 * NTOK * HID];
__device__ __nv_bfloat16 g_ch[NTOK * HID], g_cl[NTOK * HID];       // attn ctx split
__device__ __nv_bfloat16 g_fh[NTOK * FFD], g_fl[NTOK * FFD];       // gelu out split
__device__ __nv_bfloat16 g_wh[WTOT], g_wl[WTOT];                   // weights split

__device__ __forceinline__ float warpRedSum(float v) {
#pragma unroll
    for (int o = 16; o; o >>= 1) v += __shfl_xor_sync(0xffffffffu, v, o);
    return v;
}
__device__ __forceinline__ uint32_t smem_u32(const void* p) {
    return (uint32_t)__cvta_generic_to_shared(p);
}
__device__ __forceinline__ void ldsm4(uint32_t* r, uint32_t a) {
    asm volatile("ldmatrix.sync.aligned.m8n8.x4.shared.b16 {%0,%1,%2,%3},[%4];"
                 : "=r"(r[0]), "=r"(r[1]), "=r"(r[2]), "=r"(r[3]) : "r"(a));
}
__device__ __forceinline__ void ldsm4t(uint32_t* r, uint32_t a) {
    asm volatile("ldmatrix.sync.aligned.m8n8.x4.trans.shared.b16 {%0,%1,%2,%3},[%4];"
                 : "=r"(r[0]), "=r"(r[1]), "=r"(r[2]), "=r"(r[3]) : "r"(a));
}
__device__ __forceinline__ void mma16816(float* d, const uint32_t* a, const uint32_t* b) {
    asm volatile("mma.sync.aligned.m16n8k16.row.col.f32.bf16.bf16.f32 "
                 "{%0,%1,%2,%3},{%4,%5,%6,%7},{%8,%9},{%0,%1,%2,%3};"
                 : "+f"(d[0]), "+f"(d[1]), "+f"(d[2]), "+f"(d[3])
                 : "r"(a[0]), "r"(a[1]), "r"(a[2]), "r"(a[3]), "r"(b[0]), "r"(b[1]));
}
__device__ __forceinline__ void cp16(uint32_t dst, const void* src) {
    asm volatile("cp.async.cg.shared.global [%0], [%1], 16;" :: "r"(dst), "l"(src));
}
__device__ __forceinline__ void cpcommit() { asm volatile("cp.async.commit_group;"); }
__device__ __forceinline__ void cpwait0()  { asm volatile("cp.async.wait_group 0;"); }

// pack two fp32 into bf16 hi pair (ret) + lo pair (out param)
__device__ __forceinline__ uint32_t packsplit(float a, float b, uint32_t& lo) {
    __nv_bfloat16 ha = __float2bfloat16_rn(a), hb = __float2bfloat16_rn(b);
    __nv_bfloat16 la = __float2bfloat16_rn(a - __bfloat162float(ha));
    __nv_bfloat16 lb = __float2bfloat16_rn(b - __bfloat162float(hb));
    __nv_bfloat162 H(ha, hb), L(la, lb);
    lo = *(uint32_t*)&L;
    return *(uint32_t*)&H;
}

// ---------------- weight split: fp32 -> bf16 hi/lo (merged launches) ----------
__device__ __forceinline__ void wsplit_one(
    const float4* __restrict__ src, uint32_t* __restrict__ dh,
    uint32_t* __restrict__ dl, int i)
{
    float4 v = src[i];
    uint32_t lo0, lo1;
    uint32_t hi0 = packsplit(v.x, v.y, lo0);
    uint32_t hi1 = packsplit(v.z, v.w, lo1);
    dh[2 * i]     = hi0;
    dh[2 * i + 1] = hi1;
    dl[2 * i]     = lo0;
    dl[2 * i + 1] = lo1;
}

__global__ __launch_bounds__(256) void wsplit4_kernel(
    const float* __restrict__ s0, const float* __restrict__ s1,
    const float* __restrict__ s2, const float* __restrict__ s3,
    __nv_bfloat16* __restrict__ dh, __nv_bfloat16* __restrict__ dl, int n4)
{
    int i = blockIdx.x * 256 + threadIdx.x;
    if (i >= n4) return;
    int z = blockIdx.y;
    const float* s = (z == 0) ? s0 : (z == 1) ? s1 : (z == 2) ? s2 : s3;
    size_t off = (size_t)z * OFF_WK;
    wsplit_one((const float4*)s, (uint32_t*)(dh + off), (uint32_t*)(dl + off), i);
}

__global__ __launch_bounds__(256) void wsplit2_kernel(
    const float* __restrict__ s0, const float* __restrict__ s1,
    __nv_bfloat16* __restrict__ dh, __nv_bfloat16* __restrict__ dl, int n4)
{
    int i = blockIdx.x * 256 + threadIdx.x;
    if (i >= n4) return;
    int z = blockIdx.y;
    const float* s = (z == 0) ? s0 : s1;
    size_t off = OFF_W1 + (size_t)z * (OFF_W2 - OFF_W1);
    wsplit_one((const float4*)s, (uint32_t*)(dh + off), (uint32_t*)(dl + off), i);
}

// ---------------- embeddings + layernorm (one block per token) ----------------
__global__ __launch_bounds__(256) void embed_ln_kernel(
    const int* __restrict__ ids, const int* __restrict__ tids,
    const float* __restrict__ we, const float* __restrict__ pe,
    const float* __restrict__ te, const float* __restrict__ sc,
    const float* __restrict__ bi, float* __restrict__ out,
    __nv_bfloat16* __restrict__ oh, __nv_bfloat16* __restrict__ ol)
{
    int row = blockIdx.x;
    int s   = row & (SEQ - 1);
    int tid = threadIdx.x;
    int id  = ids[row];
    int tp  = tids[row];
    const float* wr = we + (size_t)id * HID;
    const float* pr = pe + (size_t)s  * HID;
    const float* tr = te + (size_t)tp * HID;

    float v[3]; float sm = 0.f, sq = 0.f;
#pragma unroll
    for (int u = 0; u < 3; u++) {
        int c = tid + 256 * u;
        float x = wr[c] + pr[c] + tr[c];
        v[u] = x; sm += x; sq += x * x;
    }
    __shared__ float sa[8], sb[8];
    sm = warpRedSum(sm); sq = warpRedSum(sq);
    int lane = tid & 31, w = tid >> 5;
    if (lane == 0) { sa[w] = sm; sb[w] = sq; }
    __syncthreads();
    sm = 0.f; sq = 0.f;
#pragma unroll
    for (int i = 0; i < 8; i++) { sm += sa[i]; sq += sb[i]; }
    float mu  = sm * (1.f / HID);
    float var = fmaxf(sq * (1.f / HID) - mu * mu, 0.f);
    float r   = rsqrtf(var + 1e-12f);
#pragma unroll
    for (int u = 0; u < 3; u++) {
        int c = tid + 256 * u;
        float x = (v[u] - mu) * r * sc[c] + bi[c];
        out[(size_t)row * HID + c] = x;
        __nv_bfloat16 h = __float2bfloat16_rn(x);
        oh[(size_t)row * HID + c] = h;
        ol[(size_t)row * HID + c] = __float2bfloat16_rn(x - __bfloat162float(h));
    }
}

// -------- layernorm over sum of 3 partials (split-K reduce fused in) ----------
__global__ __launch_bounds__(256) void ln3_kernel(
    const float* __restrict__ x, const float* __restrict__ x2,
    const float* __restrict__ x3, const float* __restrict__ sc,
    const float* __restrict__ bi, float* __restrict__ out,
    __nv_bfloat16* __restrict__ oh, __nv_bfloat16* __restrict__ ol)
{
    int row = blockIdx.x;
    int tid = threadIdx.x;
    size_t base = (size_t)row * HID;
    float v[3]; float sm = 0.f, sq = 0.f;
#pragma unroll
    for (int u = 0; u < 3; u++) {
        int c = tid + 256 * u;
        float xv = x[base + c] + x2[base + c] + x3[base + c];
        v[u] = xv; sm += xv; sq += xv * xv;
    }
    __shared__ float sa[8], sb[8];
    sm = warpRedSum(sm); sq = warpRedSum(sq);
    int lane = tid & 31, w = tid >> 5;
    if (lane == 0) { sa[w] = sm; sb[w] = sq; }
    __syncthreads();
    sm = 0.f; sq = 0.f;
#pragma unroll
    for (int i = 0; i < 8; i++) { sm += sa[i]; sq += sb[i]; }
    float mu  = sm * (1.f / HID);
    float var = fmaxf(sq * (1.f / HID) - mu * mu, 0.f);
    float r   = rsqrtf(var + 1e-12f);
#pragma unroll
    for (int u = 0; u < 3; u++) {
        int c = tid + 256 * u;
        float xv = (v[u] - mu) * r * sc[c] + bi[c];
        out[base + c] = xv;
        if (oh) {
            __nv_bfloat16 h = __float2bfloat16_rn(xv);
            oh[base + c] = h;
            ol[base + c] = __float2bfloat16_rn(xv - __bfloat162float(h));
        }
    }
}

// ============ 2-stage pipelined tensor-core GEMM, 64x128 tile, 4 warps =========
// 4 CTAs/SM (55296B smem, 128 regs x 128 thr): independent barrier groups hide
// per-chunk latency that an 8-warp CTA-wide barrier serialized.
#define SAP2 40
#define SBP2 136
#define S2_AL  5120
#define S2_BH  10240
#define S2_BL  18944
#define S2_STG 27648
#define GSMEM2 55296

// inner-loop MMA block with B_hi fragment reuse (passes share one ldsm)
#define GEMM_MMA_CHUNK(pAh, pAl, pBh, pBl)                                    \
    _Pragma("unroll")                                                         \
    for (int kh = 0; kh < 32; kh += 16) {                                     \
        uint32_t ahf[2][4], alf[2][4];                                        \
        _Pragma("unroll")                                                     \
        for (int mi = 0; mi < 2; mi++) {                                      \
            int off = (wm + mi * 16 + lr) * SAP2 + kh + lc;                   \
            ldsm4(ahf[mi], smem_u32(&(pAh)[off]));                            \
            ldsm4(alf[mi], smem_u32(&(pAl)[off]));                            \
        }                                                                     \
        _Pragma("unroll")                                                     \
        for (int np = 0; np < 4; np++) {                                      \
            uint32_t bf[4];                                                   \
            int off = (kh + lr) * SBP2 + wn + np * 16 + lc;                   \
            ldsm4t(bf, smem_u32(&(pBh)[off]));                                \
            _Pragma("unroll")                                                 \
            for (int mi = 0; mi < 2; mi++) {                                  \
                mma16816(acc[mi][np * 2],     ahf[mi], bf);                   \
                mma16816(acc[mi][np * 2 + 1], ahf[mi], bf + 2);               \
            }                                                                 \
            _Pragma("unroll")                                                 \
            for (int mi = 0; mi < 2; mi++) {                                  \
                mma16816(acc[mi][np * 2],     alf[mi], bf);                   \
                mma16816(acc[mi][np * 2 + 1], alf[mi], bf + 2);               \
            }                                                                 \
            uint32_t bfl[4];                                                  \
            ldsm4t(bfl, smem_u32(&(pBl)[off]));                               \
            _Pragma("unroll")                                                 \
            for (int mi = 0; mi < 2; mi++) {                                  \
                mma16816(acc[mi][np * 2],     ahf[mi], bfl);                  \
                mma16816(acc[mi][np * 2 + 1], ahf[mi], bfl + 2);              \
            }                                                                 \
        }                                                                     \
    }

// shared prologue/pipeline/epilogue for the 64x128 tile
#define GEMM_PIPE_DECLS()                                                     \
    extern __shared__ char dsm[];                                             \
    uint32_t sbase = smem_u32(dsm);                                           \
    int tid = threadIdx.x, lane = tid & 31, wid = tid >> 5;                   \
    int wm = (wid & 1) * 32, wn = (wid >> 1) * 64;                            \
    int lr = lane & 15, lc = (lane >> 4) * 8;                                 \
    int arow = tid >> 1, ac = (tid & 1) * 16;                                 \
    int brow = tid >> 2, bc = (tid & 3) * 32;                                 \
    uint32_t sa = sbase + (arow * SAP2 + ac) * 2;                             \
    uint32_t sb = sbase + S2_BH + (brow * SBP2 + bc) * 2;                     \
    float acc[2][8][4] = {};

template <bool GELU, bool HASRES, bool SPLITOUT>
__device__ __forceinline__ void gemm2_body(
    const __nv_bfloat16* __restrict__ Ah, const __nv_bfloat16* __restrict__ Al,
    const __nv_bfloat16* __restrict__ Wh, const __nv_bfloat16* __restrict__ Wl,
    const float* __restrict__ bias, const float* __restrict__ res,
    float* __restrict__ C, __nv_bfloat16* __restrict__ Ch, __nv_bfloat16* __restrict__ Cl,
    int N, int K, int row0, int col0)
{
    GEMM_PIPE_DECLS();
    const __nv_bfloat16* gAh = Ah + (size_t)(row0 + arow) * K + ac;
    const __nv_bfloat16* gAl = Al + (size_t)(row0 + arow) * K + ac;
    const __nv_bfloat16* gWh = Wh + (size_t)brow * N + col0 + bc;
    const __nv_bfloat16* gWl = Wl + (size_t)brow * N + col0 + bc;

    auto load = [&](int stage, int k0) {
        uint32_t s0 = (uint32_t)stage * S2_STG;
        cp16(sa + s0,             gAh + k0);
        cp16(sa + s0 + 16,        gAh + k0 + 8);
        cp16(sa + s0 + S2_AL,      gAl + k0);
        cp16(sa + s0 + S2_AL + 16, gAl + k0 + 8);
        const __nv_bfloat16* wh = gWh + (size_t)k0 * N;
        const __nv_bfloat16* wl = gWl + (size_t)k0 * N;
#pragma unroll
        for (int j = 0; j < 4; j++) {
            cp16(sb + s0 + j * 16,                     wh + j * 8);
            cp16(sb + s0 + (S2_BL - S2_BH) + j * 16,   wl + j * 8);
        }
    };

    int NK = K / 32;
    load(0, 0); cpcommit();
    for (int kt = 0; kt < NK; kt++) {
        cpwait0();
        __syncthreads();
        if (kt + 1 < NK) { load((kt + 1) & 1, (kt + 1) * 32); cpcommit(); }
        const char* st = dsm + (kt & 1) * S2_STG;
        const __nv_bfloat16* pAh = (const __nv_bfloat16*)st;
        const __nv_bfloat16* pAl = (const __nv_bfloat16*)(st + S2_AL);
        const __nv_bfloat16* pBh = (const __nv_bfloat16*)(st + S2_BH);
        const __nv_bfloat16* pBl = (const __nv_bfloat16*)(st + S2_BL);
        GEMM_MMA_CHUNK(pAh, pAl, pBh, pBl)
    }

    int gid = lane >> 2, qc = (lane & 3) * 2;
#pragma unroll
    for (int mi = 0; mi < 2; mi++)
#pragma unroll
    for (int half = 0; half < 2; half++) {
        int r = row0 + wm + mi * 16 + gid + half * 8;
#pragma unroll
        for (int n8 = 0; n8 < 8; n8++) {
            int c = col0 + wn + n8 * 8 + qc;
            float x0 = acc[mi][n8][half * 2 + 0] + bias[c];
            float x1 = acc[mi][n8][half * 2 + 1] + bias[c + 1];
            if (HASRES) {
                x0 += res[(size_t)r * N + c];
                x1 += res[(size_t)r * N + c + 1];
            }
            if (GELU) {
                x0 = 0.5f * x0 * (1.f + erff(x0 * 0.70710678118654752f));
                x1 = 0.5f * x1 * (1.f + erff(x1 * 0.70710678118654752f));
            }
            if (SPLITOUT) {
                uint32_t lo, hi = packsplit(x0, x1, lo);
                *(uint32_t*)(Ch + (size_t)r * N + c) = hi;
                *(uint32_t*)(Cl + (size_t)r * N + c) = lo;
            } else {
                *(float2*)(C + (size_t)r * N + c) = make_float2(x0, x1);
            }
        }
    }
}

template <bool GELU, bool HASRES, bool SPLITOUT>
__global__ __launch_bounds__(128, 4) void hgemm2_kernel(
    const __nv_bfloat16* __restrict__ Ah, const __nv_bfloat16* __restrict__ Al,
    const __nv_bfloat16* __restrict__ Wh, const __nv_bfloat16* __restrict__ Wl,
    const float* __restrict__ bias, const float* __restrict__ res,
    float* __restrict__ C, __nv_bfloat16* __restrict__ Ch, __nv_bfloat16* __restrict__ Cl,
    int N, int K)
{
    gemm2_body<GELU, HASRES, SPLITOUT>(Ah, Al, Wh, Wl, bias, res, C, Ch, Cl,
                                       N, K, blockIdx.y * 64, blockIdx.x * 128);
}

__global__ __launch_bounds__(128, 4) void hgemm2_qkv_kernel(
    const __nv_bfloat16* __restrict__ Ah, const __nv_bfloat16* __restrict__ Al,
    const __nv_bfloat16* __restrict__ Whb, const __nv_bfloat16* __restrict__ Wlb,
    const float* __restrict__ b0, const float* __restrict__ b1, const float* __restrict__ b2,
    __nv_bfloat16* __restrict__ Chb, __nv_bfloat16* __restrict__ Clb)
{
    int z = blockIdx.z;
    const __nv_bfloat16* Wh = Whb + (size_t)z * OFF_WK;
    const __nv_bfloat16* Wl = Wlb + (size_t)z * OFF_WK;
    const float* bias = (z == 0) ? b0 : (z == 1) ? b1 : b2;
    __nv_bfloat16* Ch = Chb + (size_t)z * NTOK * HID;
    __nv_bfloat16* Cl = Clb + (size_t)z * NTOK * HID;
    gemm2_body<false, false, true>(Ah, Al, Wh, Wl, bias, nullptr, nullptr, Ch, Cl,
                                   HID, HID, blockIdx.y * 64, blockIdx.x * 128);
}

// ---- split-K=3 GEMM: z=0 stores partial+bias+res to C0; z=1/2 raw to C1/C2 ---
__device__ __forceinline__ void gemm2_sk_body(
    const __nv_bfloat16* __restrict__ Ah, const __nv_bfloat16* __restrict__ Al,
    const __nv_bfloat16* __restrict__ Wh, const __nv_bfloat16* __restrict__ Wl,
    const float* __restrict__ bias, const float* __restrict__ res,
    float* __restrict__ Cout, bool first,
    int N, int K, int Kp, int kbase, int row0, int col0)
{
    GEMM_PIPE_DECLS();
    const __nv_bfloat16* gAh = Ah + (size_t)(row0 + arow) * K + kbase + ac;
    const __nv_bfloat16* gAl = Al + (size_t)(row0 + arow) * K + kbase + ac;
    const __nv_bfloat16* gWh = Wh + (size_t)(kbase + brow) * N + col0 + bc;
    const __nv_bfloat16* gWl = Wl + (size_t)(kbase + brow) * N + col0 + bc;

    auto load = [&](int stage, int k0) {
        uint32_t s0 = (uint32_t)stage * S2_STG;
        cp16(sa + s0,             gAh + k0);
        cp16(sa + s0 + 16,        gAh + k0 + 8);
        cp16(sa + s0 + S2_AL,      gAl + k0);
        cp16(sa + s0 + S2_AL + 16, gAl + k0 + 8);
        const __nv_bfloat16* wh = gWh + (size_t)k0 * N;
        const __nv_bfloat16* wl = gWl + (size_t)k0 * N;
#pragma unroll
        for (int j = 0; j < 4; j++) {
            cp16(sb + s0 + j * 16,                     wh + j * 8);
            cp16(sb + s0 + (S2_BL - S2_BH) + j * 16,   wl + j * 8);
        }
    };

    int NK = Kp / 32;
    load(0, 0); cpcommit();
    for (int kt = 0; kt < NK; kt++) {
        cpwait0();
        __syncthreads();
        if (kt + 1 < NK) { load((kt + 1) & 1, (kt + 1) * 32); cpcommit(); }
        const char* st = dsm + (kt & 1) * S2_STG;
        const __nv_bfloat16* pAh = (const __nv_bfloat16*)st;
        const __nv_bfloat16* pAl = (const __nv_bfloat16*)(st + S2_AL);
        const __nv_bfloat16* pBh = (const __nv_bfloat16*)(st + S2_BH);
        const __nv_bfloat16* pBl = (const __nv_bfloat16*)(st + S2_BL);
        GEMM_MMA_CHUNK(pAh, pAl, pBh, pBl)
    }

    int gid = lane >> 2, qc = (lane & 3) * 2;
#pragma unroll
    for (int mi = 0; mi < 2; mi++)
#pragma unroll
    for (int half = 0; half < 2; half++) {
        int r = row0 + wm + mi * 16 + gid + half * 8;
#pragma unroll
        for (int n8 = 0; n8 < 8; n8++) {
            int c = col0 + wn + n8 * 8 + qc;
            float x0 = acc[mi][n8][half * 2 + 0];
            float x1 = acc[mi][n8][half * 2 + 1];
            if (first) {
                x0 += bias[c]     + res[(size_t)r * N + c];
                x1 += bias[c + 1] + res[(size_t)r * N + c + 1];
            }
            *(float2*)(Cout + (size_t)r * N + c) = make_float2(x0, x1);
        }
    }
}

__global__ __launch_bounds__(128, 4) void hgemm2_sk3_kernel(
    const __nv_bfloat16* __restrict__ Ah, const __nv_bfloat16* __restrict__ Al,
    const __nv_bfloat16* __restrict__ Wh, const __nv_bfloat16* __restrict__ Wl,
    const float* __restrict__ bias, const float* __restrict__ res,
    float* __restrict__ C0, float* __restrict__ C1, float* __restrict__ C2,
    int N, int K)
{
    int z = blockIdx.z;
    int Kp = K / 3;
    float* Cout = (z == 0) ? C0 : (z == 1) ? C1 : C2;
    gemm2_sk_body(Ah, Al, Wh, Wl, bias, res, Cout, z == 0,
                  N, K, Kp, z * Kp, blockIdx.y * 64, blockIdx.x * 128);
}

// ================= flash attention (bf16 hi/lo MMA, online softmax) ============
#define FSMEM 75776
#define OQL 18432
#define OKH 36864
#define OKL 46080
#define OVH 55296
#define OVL 64512
#define OMS 73728

__global__ __launch_bounds__(256, 2) void fattn_kernel(
    const __nv_bfloat16* __restrict__ Qh, const __nv_bfloat16* __restrict__ Ql,
    const __nv_bfloat16* __restrict__ Kh, const __nv_bfloat16* __restrict__ Kl,
    const __nv_bfloat16* __restrict__ Vh, const __nv_bfloat16* __restrict__ Vl,
    const int* __restrict__ ids,
    __nv_bfloat16* __restrict__ Ch, __nv_bfloat16* __restrict__ Cl)
{
    extern __shared__ char dsm[];
    __nv_bfloat16* sQh = (__nv_bfloat16*)dsm;
    __nv_bfloat16* sQl = (__nv_bfloat16*)(dsm + OQL);
    __nv_bfloat16* sKh = (__nv_bfloat16*)(dsm + OKH);
    __nv_bfloat16* sKl = (__nv_bfloat16*)(dsm + OKL);
    __nv_bfloat16* sVh = (__nv_bfloat16*)(dsm + OVH);
    __nv_bfloat16* sVl = (__nv_bfloat16*)(dsm + OVL);
    float* sMask = (float*)(dsm + OMS);

    int tid = threadIdx.x, lane = tid & 31, wid = tid >> 5;
    int bh = blockIdx.y, b = bh / NHEAD, h = bh % NHEAD;
    int q0 = blockIdx.x * 128;
    size_t hoff = (size_t)h * DHEAD;
    size_t qrow0 = (size_t)(b * SEQ + q0);
    int lr = lane & 15, lc = (lane >> 4) * 8;

    for (int j = tid; j < SEQ; j += 256)
        sMask[j] = (ids[b * SEQ + j] == 0) ? -10000.f : 0.f;

    {   // load Q tile (128 x 64) hi/lo into smem (stride 72 elems = 144B rows)
        int r = tid >> 1, cs = (tid & 1) * 4;
        const uint4* srch = (const uint4*)(Qh + (qrow0 + r) * HID + hoff);
        const uint4* srcl = (const uint4*)(Ql + (qrow0 + r) * HID + hoff);
        uint4* dsth = (uint4*)((char*)sQh + r * 144);
        uint4* dstl = (uint4*)((char*)sQl + r * 144);
#pragma unroll
        for (int j = 0; j < 4; j++) { dsth[cs + j] = srch[cs + j]; dstl[cs + j] = srcl[cs + j]; }
    }
    __syncthreads();

    uint32_t qfh[4][4], qfl[4][4];
#pragma unroll
    for (int kc = 0; kc < 4; kc++) {
        ldsm4(qfh[kc], smem_u32(&sQh[(wid * 16 + lr) * 72 + kc * 16 + lc]));
        ldsm4(qfl[kc], smem_u32(&sQl[(wid * 16 + lr) * 72 + kc * 16 + lc]));
    }

    float m0 = -1e30f, m1 = -1e30f, l0 = 0.f, l1 = 0.f;
    float oa[8][4] = {};

    for (int kt = 0; kt < 8; kt++) {
        __syncthreads();
        {   // load K/V tile (64 x 64) hi/lo
            int r = tid >> 2, cs = (tid & 3) * 2;
            size_t grow = (size_t)(b * SEQ + kt * 64 + r) * HID + hoff;
            const uint4* skh = (const uint4*)(Kh + grow);
            const uint4* skl = (const uint4*)(Kl + grow);
            const uint4* svh = (const uint4*)(Vh + grow);
            const uint4* svl = (const uint4*)(Vl + grow);
            uint4* dkh = (uint4*)((char*)sKh + r * 144);
            uint4* dkl = (uint4*)((char*)sKl + r * 144);
            uint4* dvh = (uint4*)((char*)sVh + r * 144);
            uint4* dvl = (uint4*)((char*)sVl + r * 144);
#pragma unroll
            for (int j = 0; j < 2; j++) {
                dkh[cs + j] = skh[cs + j]; dkl[cs + j] = skl[cs + j];
                dvh[cs + j] = svh[cs + j]; dvl[cs + j] = svl[cs + j];
            }
        }
        __syncthreads();

        float scf[8][4] = {};
#pragma unroll
        for (int kc = 0; kc < 4; kc++) {
#pragma unroll
            for (int nt2 = 0; nt2 < 4; nt2++) {
                uint32_t kb[4];
                int off = (nt2 * 16 + lr) * 72 + kc * 16 + lc;
                ldsm4(kb, smem_u32(&sKh[off]));
                uint32_t b0[2] = {kb[0], kb[2]}, b1[2] = {kb[1], kb[3]};
                mma16816(scf[nt2 * 2],     qfh[kc], b0);
                mma16816(scf[nt2 * 2 + 1], qfh[kc], b1);
                mma16816(scf[nt2 * 2],     qfl[kc], b0);
                mma16816(scf[nt2 * 2 + 1], qfl[kc], b1);
                uint32_t kbl[4];
                ldsm4(kbl, smem_u32(&sKl[off]));
                uint32_t b0l[2] = {kbl[0], kbl[2]}, b1l[2] = {kbl[1], kbl[3]};
                mma16816(scf[nt2 * 2],     qfh[kc], b0l);
                mma16816(scf[nt2 * 2 + 1], qfh[kc], b1l);
            }
        }
        float tmax0 = -1e30f, tmax1 = -1e30f;
#pragma unroll
        for (int nt = 0; nt < 8; nt++) {
            int kbk = kt * 64 + (nt >> 1) * 16 + (nt & 1) * 8 + 2 * (lane & 3);
            float mb0 = sMask[kbk], mb1 = sMask[kbk + 1];
            scf[nt][0] = scf[nt][0] * 0.125f + mb0;
            scf[nt][1] = scf[nt][1] * 0.125f + mb1;
            scf[nt][2] = scf[nt][2] * 0.125f + mb0;
            scf[nt][3] = scf[nt][3] * 0.125f + mb1;
            tmax0 = fmaxf(tmax0, fmaxf(scf[nt][0], scf[nt][1]));
            tmax1 = fmaxf(tmax1, fmaxf(scf[nt][2], scf[nt][3]));
        }
        tmax0 = fmaxf(tmax0, __shfl_xor_sync(0xffffffffu, tmax0, 1));
        tmax0 = fmaxf(tmax0, __shfl_xor_sync(0xffffffffu, tmax0, 2));
        tmax1 = fmaxf(tmax1, __shfl_xor_sync(0xffffffffu, tmax1, 1));
        tmax1 = fmaxf(tmax1, __shfl_xor_sync(0xffffffffu, tmax1, 2));
        float mn0 = fmaxf(m0, tmax0), mn1 = fmaxf(m1, tmax1);
        float sc0 = __expf(m0 - mn0), sc1 = __expf(m1 - mn1);
        m0 = mn0; m1 = mn1;
        float ls0 = 0.f, ls1 = 0.f;
#pragma unroll
        for (int nt = 0; nt < 8; nt++) {
            scf[nt][0] = __expf(scf[nt][0] - m0);
            scf[nt][1] = __expf(scf[nt][1] - m0);
            scf[nt][2] = __expf(scf[nt][2] - m1);
            scf[nt][3] = __expf(scf[nt][3] - m1);
            ls0 += scf[nt][0] + scf[nt][1];
            ls1 += scf[nt][2] + scf[nt][3];
        }
        l0 = l0 * sc0 + ls0; l1 = l1 * sc1 + ls1;
#pragma unroll
        for (int j = 0; j < 8; j++) {
            oa[j][0] *= sc0; oa[j][1] *= sc0;
            oa[j][2] *= sc1; oa[j][3] *= sc1;
        }
#pragma unroll
        for (int kc = 0; kc < 4; kc++) {
            uint32_t ph[4], pl[4];
            ph[0] = packsplit(scf[kc * 2][0],     scf[kc * 2][1],     pl[0]);
            ph[1] = packsplit(scf[kc * 2][2],     scf[kc * 2][3],     pl[1]);
            ph[2] = packsplit(scf[kc * 2 + 1][0], scf[kc * 2 + 1][1], pl[2]);
            ph[3] = packsplit(scf[kc * 2 + 1][2], scf[kc * 2 + 1][3], pl[3]);
#pragma unroll
            for (int dnt = 0; dnt < 4; dnt++) {
                uint32_t vb[4];
                int off = (kc * 16 + lr) * 72 + dnt * 16 + lc;
                ldsm4t(vb, smem_u32(&sVh[off]));
                mma16816(oa[dnt * 2],     ph, vb);
                mma16816(oa[dnt * 2 + 1], ph, vb + 2);
                mma16816(oa[dnt * 2],     pl, vb);
                mma16816(oa[dnt * 2 + 1], pl, vb + 2);
                uint32_t vbl[4];
                ldsm4t(vbl, smem_u32(&sVl[off]));
                mma16816(oa[dnt * 2],     ph, vbl);
                mma16816(oa[dnt * 2 + 1], ph, vbl + 2);
            }
        }
    }

    l0 += __shfl_xor_sync(0xffffffffu, l0, 1);
    l0 += __shfl_xor_sync(0xffffffffu, l0, 2);
    l1 += __shfl_xor_sync(0xffffffffu, l1, 1);
    l1 += __shfl_xor_sync(0xffffffffu, l1, 2);
    float inv0 = 1.f / l0, inv1 = 1.f / l1;

    int r0 = lane >> 2, qc = (lane & 3) * 2;
    size_t orow0 = (qrow0 + wid * 16 + r0) * HID + hoff;
    size_t orow1 = orow0 + (size_t)8 * HID;
#pragma unroll
    for (int j = 0; j < 8; j++) {
        int col = (j >> 1) * 16 + (j & 1) * 8 + qc;
        uint32_t lo0, lo1;
        uint32_t hi0 = packsplit(oa[j][0] * inv0, oa[j][1] * inv0, lo0);
        uint32_t hi1 = packsplit(oa[j][2] * inv1, oa[j][3] * inv1, lo1);
        *(uint32_t*)(Ch + orow0 + col) = hi0;
        *(uint32_t*)(Cl + orow0 + col) = lo0;
        *(uint32_t*)(Ch + orow1 + col) = hi1;
        *(uint32_t*)(Cl + orow1 + col) = lo1;
    }
}

// ---------------- launch ----------------
extern "C" void kernel_launch(void* const* d_in, const int* in_sizes, int n_in,
                              void* d_out, int out_size)
{
    const int*   input_ids = (const int*)d_in[0];
    const int*   type_ids  = (const int*)d_in[1];
    const float* word_emb  = (const float*)d_in[2];
    const float* pos_emb   = (const float*)d_in[3];
    const float* type_emb  = (const float*)d_in[4];
    const float* e_s = (const float*)d_in[5];
    const float* e_b = (const float*)d_in[6];
    const float* wq = (const float*)d_in[7];  const float* bq = (const float*)d_in[8];
    const float* wk = (const float*)d_in[9];  const float* bk = (const float*)d_in[10];
    const float* wv = (const float*)d_in[11]; const float* bv = (const float*)d_in[12];
    const float* wo = (const float*)d_in[13]; const float* bo = (const float*)d_in[14];
    const float* l1s = (const float*)d_in[15]; const float* l1b = (const float*)d_in[16];
    const float* w1 = (const float*)d_in[17]; const float* b1 = (const float*)d_in[18];
    const float* w2 = (const float*)d_in[19]; const float* b2 = (const float*)d_in[20];
    const float* l2s = (const float*)d_in[21]; const float* l2b = (const float*)d_in[22];
    float* out = (float*)d_out;

    float *hp, *tp, *t2p, *t3p;
    __nv_bfloat16 *ahi, *alo, *qkvh, *qkvl, *chp, *clp, *fhp, *flp, *whp, *wlp;
    cudaGetSymbolAddress((void**)&hp,   g_h);
    cudaGetSymbolAddress((void**)&tp,   g_t);
    cudaGetSymbolAddress((void**)&t2p,  g_t2);
    cudaGetSymbolAddress((void**)&t3p,  g_t3);
    cudaGetSymbolAddress((void**)&ahi,  g_ahi);
    cudaGetSymbolAddress((void**)&alo,  g_alo);
    cudaGetSymbolAddress((void**)&qkvh, g_qkvh);
    cudaGetSymbolAddress((void**)&qkvl, g_qkvl);
    cudaGetSymbolAddress((void**)&chp,  g_ch);
    cudaGetSymbolAddress((void**)&clp,  g_cl);
    cudaGetSymbolAddress((void**)&fhp,  g_fh);
    cudaGetSymbolAddress((void**)&flp,  g_fl);
    cudaGetSymbolAddress((void**)&whp,  g_wh);
    cudaGetSymbolAddress((void**)&wlp,  g_wl);

    cudaFuncSetAttribute(hgemm2_kernel<true, false, true>,
                         cudaFuncAttributeMaxDynamicSharedMemorySize, GSMEM2);
    cudaFuncSetAttribute(hgemm2_qkv_kernel,
                         cudaFuncAttributeMaxDynamicSharedMemorySize, GSMEM2);
    cudaFuncSetAttribute(hgemm2_sk3_kernel,
                         cudaFuncAttributeMaxDynamicSharedMemorySize, GSMEM2);
    cudaFuncSetAttribute(fattn_kernel,
                         cudaFuncAttributeMaxDynamicSharedMemorySize, FSMEM);

    // split all weights once per replay
    {
        int n4 = (NLAYER * WSZ_QKVO) / 4;
        dim3 g4((n4 + 255) / 256, 4);
        wsplit4_kernel<<<g4, 256>>>(wq, wk, wv, wo, whp, wlp, n4);
        int n4f = (NLAYER * WSZ_FF) / 4;
        dim3 g2((n4f + 255) / 256, 2);
        wsplit2_kernel<<<g2, 256>>>(w1, w2, whp, wlp, n4f);
    }

    embed_ln_kernel<<<NTOK, 256>>>(input_ids, type_ids, word_emb, pos_emb,
                                   type_emb, e_s, e_b, hp, ahi, alo);

    dim3 gqkv(HID / 128, NTOK / 64, 3);   // (6, 64, 3)
    dim3 gsk (HID / 128, NTOK / 64, 3);   // (6, 64, 3) split-K=3
    dim3 gff (FFD / 128, NTOK / 64);      // (24, 64)
    dim3 gatt(SEQ / 128, BATCH * NHEAD);  // (4, 96)

    const int NHID = NTOK * HID;

    for (int l = 0; l < NLAYER; l++) {
        const __nv_bfloat16* Wqh = whp + OFF_WQ + (size_t)l * WSZ_QKVO;
        const __nv_bfloat16* Wql = wlp + OFF_WQ + (size_t)l * WSZ_QKVO;
        const __nv_bfloat16* Woh = whp + OFF_WO + (size_t)l * WSZ_QKVO;
        const __nv_bfloat16* Wol = wlp + OFF_WO + (size_t)l * WSZ_QKVO;
        const __nv_bfloat16* W1h = whp + OFF_W1 + (size_t)l * WSZ_FF;
        const __nv_bfloat16* W1l = wlp + OFF_W1 + (size_t)l * WSZ_FF;
        const __nv_bfloat16* W2h = whp + OFF_W2 + (size_t)l * WSZ_FF;
        const __nv_bfloat16* W2l = wlp + OFF_W2 + (size_t)l * WSZ_FF;
        const float* Bq = bq + (size_t)l * HID;
        const float* Bk = bk + (size_t)l * HID;
        const float* Bv = bv + (size_t)l * HID;
        const float* Bo = bo + (size_t)l * HID;
        const float* B1 = b1 + (size_t)l * FFD;
        const float* B2 = b2 + (size_t)l * HID;
        const float* L1s = l1s + (size_t)l * HID;
        const float* L1b = l1b + (size_t)l * HID;
        const float* L2s = l2s + (size_t)l * HID;
        const float* L2b = l2b + (size_t)l * HID;

        hgemm2_qkv_kernel<<<gqkv, 128, GSMEM2>>>(ahi, alo, Wqh, Wql,
                                                 Bq, Bk, Bv, qkvh, qkvl);

        fattn_kernel<<<gatt, 256, FSMEM>>>(
            qkvh, qkvl, qkvh + NHID, qkvl + NHID, qkvh + 2 * NHID, qkvl + 2 * NHID,
            input_ids, chp, clp);

        hgemm2_sk3_kernel<<<gsk, 128, GSMEM2>>>(
            chp, clp, Woh, Wol, Bo, hp, tp, t2p, t3p, HID, HID);
        ln3_kernel<<<NTOK, 256>>>(tp, t2p, t3p, L1s, L1b, hp, ahi, alo);

        hgemm2_kernel<true, false, true><<<gff, 128, GSMEM2>>>(
            ahi, alo, W1h, W1l, B1, nullptr, nullptr, fhp, flp, FFD, HID);

        hgemm2_sk3_kernel<<<gsk, 128, GSMEM2>>>(
            fhp, flp, W2h, W2l, B2, hp, tp, t2p, t3p, HID, FFD);

        if (l == NLAYER - 1)
            ln3_kernel<<<NTOK, 256>>>(tp, t2p, t3p, L2s, L2b, out, nullptr, nullptr);
        else
            ln3_kernel<<<NTOK, 256>>>(tp, t2p, t3p, L2s, L2b, hp, ahi, alo);
    }
}

// round 13
// speedup vs baseline: 1.1291x; 1.1291x over previous
#include <cuda_runtime.h>
#include <cuda_bf16.h>
#include <math.h>
#include <stdint.h>

#define HID    768
#define SEQ    512
#define BATCH  8
#define NHEAD  12
#define DHEAD  64
#define FFD    3072
#define NLAYER 12
#define NTOK   4096   // BATCH*SEQ

// weight split buffer layout (element offsets into g_wh/g_wl)
#define WSZ_QKVO 589824            // 768*768
#define WSZ_FF   2359296           // 768*3072
#define OFF_WQ   0
#define OFF_WK   7077888
#define OFF_WV   14155776
#define OFF_WO   21233664
#define OFF_W1   28311552
#define OFF_W2   56623104
#define WTOT     84934656

// ---------------- scratch (device globals; no allocation allowed) ----------------
__device__ float g_h[NTOK * HID];          // fp32 residual stream
__device__ float g_t[NTOK * HID];          // split-K partial 0 + bias + res
__device__ float g_t2[NTOK * HID];         // split-K partial 1
__device__ float g_t3[NTOK * HID];         // split-K partial 2
__device__ __nv_bfloat16 g_ahi[NTOK * HID], g_alo[NTOK * HID];     // LN out split
__device__ __nv_bfloat16 g_qkvh[3 * NTOK * HID], g_qkvl[3 * NTOK * HID];
__device__ __nv_bfloat16 g_ch[NTOK * HID], g_cl[NTOK * HID];       // attn ctx split
__device__ __nv_bfloat16 g_fh[NTOK * FFD], g_fl[NTOK * FFD];       // gelu out split
__device__ __nv_bfloat16 g_wh[WTOT], g_wl[WTOT];                   // weights split

__device__ __forceinline__ float warpRedSum(float v) {
#pragma unroll
    for (int o = 16; o; o >>= 1) v += __shfl_xor_sync(0xffffffffu, v, o);
    return v;
}
__device__ __forceinline__ uint32_t smem_u32(const void* p) {
    return (uint32_t)__cvta_generic_to_shared(p);
}
__device__ __forceinline__ void ldsm4(uint32_t* r, uint32_t a) {
    asm volatile("ldmatrix.sync.aligned.m8n8.x4.shared.b16 {%0,%1,%2,%3},[%4];"
                 : "=r"(r[0]), "=r"(r[1]), "=r"(r[2]), "=r"(r[3]) : "r"(a));
}
__device__ __forceinline__ void ldsm4t(uint32_t* r, uint32_t a) {
    asm volatile("ldmatrix.sync.aligned.m8n8.x4.trans.shared.b16 {%0,%1,%2,%3},[%4];"
                 : "=r"(r[0]), "=r"(r[1]), "=r"(r[2]), "=r"(r[3]) : "r"(a));
}
__device__ __forceinline__ void mma16816(float* d, const uint32_t* a, const uint32_t* b) {
    asm volatile("mma.sync.aligned.m16n8k16.row.col.f32.bf16.bf16.f32 "
                 "{%0,%1,%2,%3},{%4,%5,%6,%7},{%8,%9},{%0,%1,%2,%3};"
                 : "+f"(d[0]), "+f"(d[1]), "+f"(d[2]), "+f"(d[3])
                 : "r"(a[0]), "r"(a[1]), "r"(a[2]), "r"(a[3]), "r"(b[0]), "r"(b[1]));
}
__device__ __forceinline__ void cp16(uint32_t dst, const void* src) {
    asm volatile("cp.async.cg.shared.global [%0], [%1], 16;" :: "r"(dst), "l"(src));
}
__device__ __forceinline__ void cpcommit() { asm volatile("cp.async.commit_group;"); }
__device__ __forceinline__ void cpwait0()  { asm volatile("cp.async.wait_group 0;"); }
__device__ __forceinline__ void cpwait1()  { asm volatile("cp.async.wait_group 1;"); }

// pack two fp32 into bf16 hi pair (ret) + lo pair (out param)
__device__ __forceinline__ uint32_t packsplit(float a, float b, uint32_t& lo) {
    __nv_bfloat16 ha = __float2bfloat16_rn(a), hb = __float2bfloat16_rn(b);
    __nv_bfloat16 la = __float2bfloat16_rn(a - __bfloat162float(ha));
    __nv_bfloat16 lb = __float2bfloat16_rn(b - __bfloat162float(hb));
    __nv_bfloat162 H(ha, hb), L(la, lb);
    lo = *(uint32_t*)&L;
    return *(uint32_t*)&H;
}

// ---------------- weight split: fp32 -> bf16 hi/lo (merged launches) ----------
__device__ __forceinline__ void wsplit_one(
    const float4* __restrict__ src, uint32_t* __restrict__ dh,
    uint32_t* __restrict__ dl, int i)
{
    float4 v = src[i];
    uint32_t lo0, lo1;
    uint32_t hi0 = packsplit(v.x, v.y, lo0);
    uint32_t hi1 = packsplit(v.z, v.w, lo1);
    dh[2 * i]     = hi0;
    dh[2 * i + 1] = hi1;
    dl[2 * i]     = lo0;
    dl[2 * i + 1] = lo1;
}

__global__ __launch_bounds__(256) void wsplit4_kernel(
    const float* __restrict__ s0, const float* __restrict__ s1,
    const float* __restrict__ s2, const float* __restrict__ s3,
    __nv_bfloat16* __restrict__ dh, __nv_bfloat16* __restrict__ dl, int n4)
{
    int i = blockIdx.x * 256 + threadIdx.x;
    if (i >= n4) return;
    int z = blockIdx.y;
    const float* s = (z == 0) ? s0 : (z == 1) ? s1 : (z == 2) ? s2 : s3;
    size_t off = (size_t)z * OFF_WK;
    wsplit_one((const float4*)s, (uint32_t*)(dh + off), (uint32_t*)(dl + off), i);
}

__global__ __launch_bounds__(256) void wsplit2_kernel(
    const float* __restrict__ s0, const float* __restrict__ s1,
    __nv_bfloat16* __restrict__ dh, __nv_bfloat16* __restrict__ dl, int n4)
{
    int i = blockIdx.x * 256 + threadIdx.x;
    if (i >= n4) return;
    int z = blockIdx.y;
    const float* s = (z == 0) ? s0 : s1;
    size_t off = OFF_W1 + (size_t)z * (OFF_W2 - OFF_W1);
    wsplit_one((const float4*)s, (uint32_t*)(dh + off), (uint32_t*)(dl + off), i);
}

// ---------------- embeddings + layernorm (one block per token) ----------------
__global__ __launch_bounds__(256) void embed_ln_kernel(
    const int* __restrict__ ids, const int* __restrict__ tids,
    const float* __restrict__ we, const float* __restrict__ pe,
    const float* __restrict__ te, const float* __restrict__ sc,
    const float* __restrict__ bi, float* __restrict__ out,
    __nv_bfloat16* __restrict__ oh, __nv_bfloat16* __restrict__ ol)
{
    int row = blockIdx.x;
    int s   = row & (SEQ - 1);
    int tid = threadIdx.x;
    int id  = ids[row];
    int tp  = tids[row];
    const float* wr = we + (size_t)id * HID;
    const float* pr = pe + (size_t)s  * HID;
    const float* tr = te + (size_t)tp * HID;

    float v[3]; float sm = 0.f, sq = 0.f;
#pragma unroll
    for (int u = 0; u < 3; u++) {
        int c = tid + 256 * u;
        float x = wr[c] + pr[c] + tr[c];
        v[u] = x; sm += x; sq += x * x;
    }
    __shared__ float sa[8], sb[8];
    sm = warpRedSum(sm); sq = warpRedSum(sq);
    int lane = tid & 31, w = tid >> 5;
    if (lane == 0) { sa[w] = sm; sb[w] = sq; }
    __syncthreads();
    sm = 0.f; sq = 0.f;
#pragma unroll
    for (int i = 0; i < 8; i++) { sm += sa[i]; sq += sb[i]; }
    float mu  = sm * (1.f / HID);
    float var = fmaxf(sq * (1.f / HID) - mu * mu, 0.f);
    float r   = rsqrtf(var + 1e-12f);
#pragma unroll
    for (int u = 0; u < 3; u++) {
        int c = tid + 256 * u;
        float x = (v[u] - mu) * r * sc[c] + bi[c];
        out[(size_t)row * HID + c] = x;
        __nv_bfloat16 h = __float2bfloat16_rn(x);
        oh[(size_t)row * HID + c] = h;
        ol[(size_t)row * HID + c] = __float2bfloat16_rn(x - __bfloat162float(h));
    }
}

// -------- layernorm over sum of 3 partials (split-K reduce fused in) ----------
__global__ __launch_bounds__(256) void ln3_kernel(
    const float* __restrict__ x, const float* __restrict__ x2,
    const float* __restrict__ x3, const float* __restrict__ sc,
    const float* __restrict__ bi, float* __restrict__ out,
    __nv_bfloat16* __restrict__ oh, __nv_bfloat16* __restrict__ ol)
{
    int row = blockIdx.x;
    int tid = threadIdx.x;
    size_t base = (size_t)row * HID;
    float v[3]; float sm = 0.f, sq = 0.f;
#pragma unroll
    for (int u = 0; u < 3; u++) {
        int c = tid + 256 * u;
        float xv = x[base + c] + x2[base + c] + x3[base + c];
        v[u] = xv; sm += xv; sq += xv * xv;
    }
    __shared__ float sa[8], sb[8];
    sm = warpRedSum(sm); sq = warpRedSum(sq);
    int lane = tid & 31, w = tid >> 5;
    if (lane == 0) { sa[w] = sm; sb[w] = sq; }
    __syncthreads();
    sm = 0.f; sq = 0.f;
#pragma unroll
    for (int i = 0; i < 8; i++) { sm += sa[i]; sq += sb[i]; }
    float mu  = sm * (1.f / HID);
    float var = fmaxf(sq * (1.f / HID) - mu * mu, 0.f);
    float r   = rsqrtf(var + 1e-12f);
#pragma unroll
    for (int u = 0; u < 3; u++) {
        int c = tid + 256 * u;
        float xv = (v[u] - mu) * r * sc[c] + bi[c];
        out[base + c] = xv;
        if (oh) {
            __nv_bfloat16 h = __float2bfloat16_rn(xv);
            oh[base + c] = h;
            ol[base + c] = __float2bfloat16_rn(xv - __bfloat162float(h));
        }
    }
}

// ================= 3-stage pipelined tensor-core GEMM (bf16 hi/lo) =============
// 128x128 tile, 256 threads, 2 CTAs/SM. B fragments software-pipelined: the
// ldsm4t for np+1 issues before np's 12 MMAs, hiding ~30cyc LDS latency.
#define SAP2 40
#define SBP2 136
#define OFA_L 10240
#define OFB_H 20480
#define OFB_L 29184
#define STAGEB 37888
#define GSMEM  113664    // 3 stages

#define GEMM_MMA_CHUNK(pAh, pAl, pBh, pBl)                                    \
    _Pragma("unroll")                                                         \
    for (int kh = 0; kh < 32; kh += 16) {                                     \
        uint32_t ahf[2][4], alf[2][4];                                        \
        _Pragma("unroll")                                                     \
        for (int mi = 0; mi < 2; mi++) {                                      \
            int off = (wm + mi * 16 + lr) * SAP2 + kh + lc;                   \
            ldsm4(ahf[mi], smem_u32(&(pAh)[off]));                            \
            ldsm4(alf[mi], smem_u32(&(pAl)[off]));                            \
        }                                                                     \
        uint32_t bfh[2][4], bfl[2][4];                                        \
        {                                                                     \
            int off0 = (kh + lr) * SBP2 + wn + lc;                            \
            ldsm4t(bfh[0], smem_u32(&(pBh)[off0]));                           \
            ldsm4t(bfl[0], smem_u32(&(pBl)[off0]));                           \
        }                                                                     \
        _Pragma("unroll")                                                     \
        for (int np = 0; np < 4; np++) {                                      \
            int cur = np & 1, nxt = cur ^ 1;                                  \
            if (np < 3) {                                                     \
                int offn = (kh + lr) * SBP2 + wn + (np + 1) * 16 + lc;        \
                ldsm4t(bfh[nxt], smem_u32(&(pBh)[offn]));                     \
                ldsm4t(bfl[nxt], smem_u32(&(pBl)[offn]));                     \
            }                                                                 \
            _Pragma("unroll")                                                 \
            for (int mi = 0; mi < 2; mi++) {                                  \
                mma16816(acc[mi][np * 2],     ahf[mi], bfh[cur]);             \
                mma16816(acc[mi][np * 2 + 1], ahf[mi], bfh[cur] + 2);         \
            }                                                                 \
            _Pragma("unroll")                                                 \
            for (int mi = 0; mi < 2; mi++) {                                  \
                mma16816(acc[mi][np * 2],     alf[mi], bfh[cur]);             \
                mma16816(acc[mi][np * 2 + 1], alf[mi], bfh[cur] + 2);         \
            }                                                                 \
            _Pragma("unroll")                                                 \
            for (int mi = 0; mi < 2; mi++) {                                  \
                mma16816(acc[mi][np * 2],     ahf[mi], bfl[cur]);             \
                mma16816(acc[mi][np * 2 + 1], ahf[mi], bfl[cur] + 2);         \
            }                                                                 \
        }                                                                     \
    }

template <bool GELU, bool HASRES, bool SPLITOUT>
__device__ __forceinline__ void gemm2_body(
    const __nv_bfloat16* __restrict__ Ah, const __nv_bfloat16* __restrict__ Al,
    const __nv_bfloat16* __restrict__ Wh, const __nv_bfloat16* __restrict__ Wl,
    const float* __restrict__ bias, const float* __restrict__ res,
    float* __restrict__ C, __nv_bfloat16* __restrict__ Ch, __nv_bfloat16* __restrict__ Cl,
    int N, int K, int row0, int col0)
{
    extern __shared__ char dsm[];
    uint32_t sbase = smem_u32(dsm);
    int tid = threadIdx.x, lane = tid & 31, wid = tid >> 5;
    int wm = (wid & 3) * 32, wn = (wid >> 2) * 64;
    int lr = lane & 15, lc = (lane >> 4) * 8;

    int arow = tid >> 1, ac = (tid & 1) * 16;
    int brow = tid >> 3, bc = (tid & 7) * 16;
    const __nv_bfloat16* gAh = Ah + (size_t)(row0 + arow) * K + ac;
    const __nv_bfloat16* gAl = Al + (size_t)(row0 + arow) * K + ac;
    const __nv_bfloat16* gWh = Wh + (size_t)brow * N + col0 + bc;
    const __nv_bfloat16* gWl = Wl + (size_t)brow * N + col0 + bc;
    uint32_t sa = sbase + (arow * SAP2 + ac) * 2;
    uint32_t sb = sbase + OFB_H + (brow * SBP2 + bc) * 2;

    float acc[2][8][4] = {};

    auto load = [&](int stage, int k0) {
        uint32_t s0 = (uint32_t)stage * STAGEB;
        cp16(sa + s0,              gAh + k0);
        cp16(sa + s0 + 16,         gAh + k0 + 8);
        cp16(sa + s0 + OFA_L,      gAl + k0);
        cp16(sa + s0 + OFA_L + 16, gAl + k0 + 8);
        const __nv_bfloat16* wh = gWh + (size_t)k0 * N;
        const __nv_bfloat16* wl = gWl + (size_t)k0 * N;
        cp16(sb + s0,                       wh);
        cp16(sb + s0 + 16,                  wh + 8);
        cp16(sb + s0 + (OFB_L - OFB_H),      wl);
        cp16(sb + s0 + (OFB_L - OFB_H) + 16, wl + 8);
    };

    int NK = K / 32;
    load(0, 0); cpcommit();
    load(1, 32); cpcommit();

    for (int kt = 0; kt < NK; kt++) {
        if (kt + 1 < NK) cpwait1(); else cpwait0();
        __syncthreads();
        if (kt + 2 < NK) {
            int s2 = (kt + 2) - ((kt + 2) / 3) * 3;
            load(s2, (kt + 2) * 32); cpcommit();
        }
        const char* st = dsm + (kt - (kt / 3) * 3) * STAGEB;
        const __nv_bfloat16* pAh = (const __nv_bfloat16*)st;
        const __nv_bfloat16* pAl = (const __nv_bfloat16*)(st + OFA_L);
        const __nv_bfloat16* pBh = (const __nv_bfloat16*)(st + OFB_H);
        const __nv_bfloat16* pBl = (const __nv_bfloat16*)(st + OFB_L);
        GEMM_MMA_CHUNK(pAh, pAl, pBh, pBl)
    }

    int gid = lane >> 2, qc = (lane & 3) * 2;
#pragma unroll
    for (int mi = 0; mi < 2; mi++)
#pragma unroll
    for (int half = 0; half < 2; half++) {
        int r = row0 + wm + mi * 16 + gid + half * 8;
#pragma unroll
        for (int n8 = 0; n8 < 8; n8++) {
            int c = col0 + wn + n8 * 8 + qc;
            float x0 = acc[mi][n8][half * 2 + 0] + bias[c];
            float x1 = acc[mi][n8][half * 2 + 1] + bias[c + 1];
            if (HASRES) {
                x0 += res[(size_t)r * N + c];
                x1 += res[(size_t)r * N + c + 1];
            }
            if (GELU) {
                x0 = 0.5f * x0 * (1.f + erff(x0 * 0.70710678118654752f));
                x1 = 0.5f * x1 * (1.f + erff(x1 * 0.70710678118654752f));
            }
            if (SPLITOUT) {
                uint32_t lo, hi = packsplit(x0, x1, lo);
                *(uint32_t*)(Ch + (size_t)r * N + c) = hi;
                *(uint32_t*)(Cl + (size_t)r * N + c) = lo;
            } else {
                *(float2*)(C + (size_t)r * N + c) = make_float2(x0, x1);
            }
        }
    }
}

template <bool GELU, bool HASRES, bool SPLITOUT>
__global__ __launch_bounds__(256, 2) void hgemm2_kernel(
    const __nv_bfloat16* __restrict__ Ah, const __nv_bfloat16* __restrict__ Al,
    const __nv_bfloat16* __restrict__ Wh, const __nv_bfloat16* __restrict__ Wl,
    const float* __restrict__ bias, const float* __restrict__ res,
    float* __restrict__ C, __nv_bfloat16* __restrict__ Ch, __nv_bfloat16* __restrict__ Cl,
    int N, int K)
{
    gemm2_body<GELU, HASRES, SPLITOUT>(Ah, Al, Wh, Wl, bias, res, C, Ch, Cl,
                                       N, K, blockIdx.y * 128, blockIdx.x * 128);
}

__global__ __launch_bounds__(256, 2) void hgemm2_qkv_kernel(
    const __nv_bfloat16* __restrict__ Ah, const __nv_bfloat16* __restrict__ Al,
    const __nv_bfloat16* __restrict__ Whb, const __nv_bfloat16* __restrict__ Wlb,
    const float* __restrict__ b0, const float* __restrict__ b1, const float* __restrict__ b2,
    __nv_bfloat16* __restrict__ Chb, __nv_bfloat16* __restrict__ Clb)
{
    int z = blockIdx.z;
    const __nv_bfloat16* Wh = Whb + (size_t)z * OFF_WK;
    const __nv_bfloat16* Wl = Wlb + (size_t)z * OFF_WK;
    const float* bias = (z == 0) ? b0 : (z == 1) ? b1 : b2;
    __nv_bfloat16* Ch = Chb + (size_t)z * NTOK * HID;
    __nv_bfloat16* Cl = Clb + (size_t)z * NTOK * HID;
    gemm2_body<false, false, true>(Ah, Al, Wh, Wl, bias, nullptr, nullptr, Ch, Cl,
                                   HID, HID, blockIdx.y * 128, blockIdx.x * 128);
}

// ---- split-K=3 GEMM: z=0 stores partial+bias+res to C0; z=1/2 raw to C1/C2 ---
__device__ __forceinline__ void gemm2_sk_body(
    const __nv_bfloat16* __restrict__ Ah, const __nv_bfloat16* __restrict__ Al,
    const __nv_bfloat16* __restrict__ Wh, const __nv_bfloat16* __restrict__ Wl,
    const float* __restrict__ bias, const float* __restrict__ res,
    float* __restrict__ Cout, bool first,
    int N, int K, int Kp, int kbase, int row0, int col0)
{
    extern __shared__ char dsm[];
    uint32_t sbase = smem_u32(dsm);
    int tid = threadIdx.x, lane = tid & 31, wid = tid >> 5;
    int wm = (wid & 3) * 32, wn = (wid >> 2) * 64;
    int lr = lane & 15, lc = (lane >> 4) * 8;

    int arow = tid >> 1, ac = (tid & 1) * 16;
    int brow = tid >> 3, bc = (tid & 7) * 16;
    const __nv_bfloat16* gAh = Ah + (size_t)(row0 + arow) * K + kbase + ac;
    const __nv_bfloat16* gAl = Al + (size_t)(row0 + arow) * K + kbase + ac;
    const __nv_bfloat16* gWh = Wh + (size_t)(kbase + brow) * N + col0 + bc;
    const __nv_bfloat16* gWl = Wl + (size_t)(kbase + brow) * N + col0 + bc;
    uint32_t sa = sbase + (arow * SAP2 + ac) * 2;
    uint32_t sb = sbase + OFB_H + (brow * SBP2 + bc) * 2;

    float acc[2][8][4] = {};

    auto load = [&](int stage, int k0) {
        uint32_t s0 = (uint32_t)stage * STAGEB;
        cp16(sa + s0,              gAh + k0);
        cp16(sa + s0 + 16,         gAh + k0 + 8);
        cp16(sa + s0 + OFA_L,      gAl + k0);
        cp16(sa + s0 + OFA_L + 16, gAl + k0 + 8);
        const __nv_bfloat16* wh = gWh + (size_t)k0 * N;
        const __nv_bfloat16* wl = gWl + (size_t)k0 * N;
        cp16(sb + s0,                       wh);
        cp16(sb + s0 + 16,                  wh + 8);
        cp16(sb + s0 + (OFB_L - OFB_H),      wl);
        cp16(sb + s0 + (OFB_L - OFB_H) + 16, wl + 8);
    };

    int NK = Kp / 32;
    load(0, 0); cpcommit();
    load(1, 32); cpcommit();

    for (int kt = 0; kt < NK; kt++) {
        if (kt + 1 < NK) cpwait1(); else cpwait0();
        __syncthreads();
        if (kt + 2 < NK) {
            int s2 = (kt + 2) - ((kt + 2) / 3) * 3;
            load(s2, (kt + 2) * 32); cpcommit();
        }
        const char* st = dsm + (kt - (kt / 3) * 3) * STAGEB;
        const __nv_bfloat16* pAh = (const __nv_bfloat16*)st;
        const __nv_bfloat16* pAl = (const __nv_bfloat16*)(st + OFA_L);
        const __nv_bfloat16* pBh = (const __nv_bfloat16*)(st + OFB_H);
        const __nv_bfloat16* pBl = (const __nv_bfloat16*)(st + OFB_L);
        GEMM_MMA_CHUNK(pAh, pAl, pBh, pBl)
    }

    int gid = lane >> 2, qc = (lane & 3) * 2;
#pragma unroll
    for (int mi = 0; mi < 2; mi++)
#pragma unroll
    for (int half = 0; half < 2; half++) {
        int r = row0 + wm + mi * 16 + gid + half * 8;
#pragma unroll
        for (int n8 = 0; n8 < 8; n8++) {
            int c = col0 + wn + n8 * 8 + qc;
            float x0 = acc[mi][n8][half * 2 + 0];
            float x1 = acc[mi][n8][half * 2 + 1];
            if (first) {
                x0 += bias[c]     + res[(size_t)r * N + c];
                x1 += bias[c + 1] + res[(size_t)r * N + c + 1];
            }
            *(float2*)(Cout + (size_t)r * N + c) = make_float2(x0, x1);
        }
    }
}

__global__ __launch_bounds__(256, 2) void hgemm2_sk3_kernel(
    const __nv_bfloat16* __restrict__ Ah, const __nv_bfloat16* __restrict__ Al,
    const __nv_bfloat16* __restrict__ Wh, const __nv_bfloat16* __restrict__ Wl,
    const float* __restrict__ bias, const float* __restrict__ res,
    float* __restrict__ C0, float* __restrict__ C1, float* __restrict__ C2,
    int N, int K)
{
    int z = blockIdx.z;
    int Kp = K / 3;
    float* Cout = (z == 0) ? C0 : (z == 1) ? C1 : C2;
    gemm2_sk_body(Ah, Al, Wh, Wl, bias, res, Cout, z == 0,
                  N, K, Kp, z * Kp, blockIdx.y * 128, blockIdx.x * 128);
}

// ================= flash attention (bf16 hi/lo MMA, online softmax) ============
#define FSMEM 75776
#define OQL 18432
#define OKH 36864
#define OKL 46080
#define OVH 55296
#define OVL 64512
#define OMS 73728

__global__ __launch_bounds__(256, 2) void fattn_kernel(
    const __nv_bfloat16* __restrict__ Qh, const __nv_bfloat16* __restrict__ Ql,
    const __nv_bfloat16* __restrict__ Kh, const __nv_bfloat16* __restrict__ Kl,
    const __nv_bfloat16* __restrict__ Vh, const __nv_bfloat16* __restrict__ Vl,
    const int* __restrict__ ids,
    __nv_bfloat16* __restrict__ Ch, __nv_bfloat16* __restrict__ Cl)
{
    extern __shared__ char dsm[];
    __nv_bfloat16* sQh = (__nv_bfloat16*)dsm;
    __nv_bfloat16* sQl = (__nv_bfloat16*)(dsm + OQL);
    __nv_bfloat16* sKh = (__nv_bfloat16*)(dsm + OKH);
    __nv_bfloat16* sKl = (__nv_bfloat16*)(dsm + OKL);
    __nv_bfloat16* sVh = (__nv_bfloat16*)(dsm + OVH);
    __nv_bfloat16* sVl = (__nv_bfloat16*)(dsm + OVL);
    float* sMask = (float*)(dsm + OMS);

    int tid = threadIdx.x, lane = tid & 31, wid = tid >> 5;
    int bh = blockIdx.y, b = bh / NHEAD, h = bh % NHEAD;
    int q0 = blockIdx.x * 128;
    size_t hoff = (size_t)h * DHEAD;
    size_t qrow0 = (size_t)(b * SEQ + q0);
    int lr = lane & 15, lc = (lane >> 4) * 8;

    for (int j = tid; j < SEQ; j += 256)
        sMask[j] = (ids[b * SEQ + j] == 0) ? -10000.f : 0.f;

    {   // load Q tile (128 x 64) hi/lo into smem (stride 72 elems = 144B rows)
        int r = tid >> 1, cs = (tid & 1) * 4;
        const uint4* srch = (const uint4*)(Qh + (qrow0 + r) * HID + hoff);
        const uint4* srcl = (const uint4*)(Ql + (qrow0 + r) * HID + hoff);
        uint4* dsth = (uint4*)((char*)sQh + r * 144);
        uint4* dstl = (uint4*)((char*)sQl + r * 144);
#pragma unroll
        for (int j = 0; j < 4; j++) { dsth[cs + j] = srch[cs + j]; dstl[cs + j] = srcl[cs + j]; }
    }
    __syncthreads();

    uint32_t qfh[4][4], qfl[4][4];
#pragma unroll
    for (int kc = 0; kc < 4; kc++) {
        ldsm4(qfh[kc], smem_u32(&sQh[(wid * 16 + lr) * 72 + kc * 16 + lc]));
        ldsm4(qfl[kc], smem_u32(&sQl[(wid * 16 + lr) * 72 + kc * 16 + lc]));
    }

    float m0 = -1e30f, m1 = -1e30f, l0 = 0.f, l1 = 0.f;
    float oa[8][4] = {};

    for (int kt = 0; kt < 8; kt++) {
        __syncthreads();
        {   // load K/V tile (64 x 64) hi/lo
            int r = tid >> 2, cs = (tid & 3) * 2;
            size_t grow = (size_t)(b * SEQ + kt * 64 + r) * HID + hoff;
            const uint4* skh = (const uint4*)(Kh + grow);
            const uint4* skl = (const uint4*)(Kl + grow);
            const uint4* svh = (const uint4*)(Vh + grow);
            const uint4* svl = (const uint4*)(Vl + grow);
            uint4* dkh = (uint4*)((char*)sKh + r * 144);
            uint4* dkl = (uint4*)((char*)sKl + r * 144);
            uint4* dvh = (uint4*)((char*)sVh + r * 144);
            uint4* dvl = (uint4*)((char*)sVl + r * 144);
#pragma unroll
            for (int j = 0; j < 2; j++) {
                dkh[cs + j] = skh[cs + j]; dkl[cs + j] = skl[cs + j];
                dvh[cs + j] = svh[cs + j]; dvl[cs + j] = svl[cs + j];
            }
        }
        __syncthreads();

        float scf[8][4] = {};
#pragma unroll
        for (int kc = 0; kc < 4; kc++) {
#pragma unroll
            for (int nt2 = 0; nt2 < 4; nt2++) {
                uint32_t kb[4];
                int off = (nt2 * 16 + lr) * 72 + kc * 16 + lc;
                ldsm4(kb, smem_u32(&sKh[off]));
                uint32_t b0[2] = {kb[0], kb[2]}, b1[2] = {kb[1], kb[3]};
                mma16816(scf[nt2 * 2],     qfh[kc], b0);
                mma16816(scf[nt2 * 2 + 1], qfh[kc], b1);
                mma16816(scf[nt2 * 2],     qfl[kc], b0);
                mma16816(scf[nt2 * 2 + 1], qfl[kc], b1);
                uint32_t kbl[4];
                ldsm4(kbl, smem_u32(&sKl[off]));
                uint32_t b0l[2] = {kbl[0], kbl[2]}, b1l[2] = {kbl[1], kbl[3]};
                mma16816(scf[nt2 * 2],     qfh[kc], b0l);
                mma16816(scf[nt2 * 2 + 1], qfh[kc], b1l);
            }
        }
        float tmax0 = -1e30f, tmax1 = -1e30f;
#pragma unroll
        for (int nt = 0; nt < 8; nt++) {
            int kbk = kt * 64 + (nt >> 1) * 16 + (nt & 1) * 8 + 2 * (lane & 3);
            float mb0 = sMask[kbk], mb1 = sMask[kbk + 1];
            scf[nt][0] = scf[nt][0] * 0.125f + mb0;
            scf[nt][1] = scf[nt][1] * 0.125f + mb1;
            scf[nt][2] = scf[nt][2] * 0.125f + mb0;
            scf[nt][3] = scf[nt][3] * 0.125f + mb1;
            tmax0 = fmaxf(tmax0, fmaxf(scf[nt][0], scf[nt][1]));
            tmax1 = fmaxf(tmax1, fmaxf(scf[nt][2], scf[nt][3]));
        }
        tmax0 = fmaxf(tmax0, __shfl_xor_sync(0xffffffffu, tmax0, 1));
        tmax0 = fmaxf(tmax0, __shfl_xor_sync(0xffffffffu, tmax0, 2));
        tmax1 = fmaxf(tmax1, __shfl_xor_sync(0xffffffffu, tmax1, 1));
        tmax1 = fmaxf(tmax1, __shfl_xor_sync(0xffffffffu, tmax1, 2));
        float mn0 = fmaxf(m0, tmax0), mn1 = fmaxf(m1, tmax1);
        float sc0 = __expf(m0 - mn0), sc1 = __expf(m1 - mn1);
        m0 = mn0; m1 = mn1;
        float ls0 = 0.f, ls1 = 0.f;
#pragma unroll
        for (int nt = 0; nt < 8; nt++) {
            scf[nt][0] = __expf(scf[nt][0] - m0);
            scf[nt][1] = __expf(scf[nt][1] - m0);
            scf[nt][2] = __expf(scf[nt][2] - m1);
            scf[nt][3] = __expf(scf[nt][3] - m1);
            ls0 += scf[nt][0] + scf[nt][1];
            ls1 += scf[nt][2] + scf[nt][3];
        }
        l0 = l0 * sc0 + ls0; l1 = l1 * sc1 + ls1;
#pragma unroll
        for (int j = 0; j < 8; j++) {
            oa[j][0] *= sc0; oa[j][1] *= sc0;
            oa[j][2] *= sc1; oa[j][3] *= sc1;
        }
#pragma unroll
        for (int kc = 0; kc < 4; kc++) {
            uint32_t ph[4], pl[4];
            ph[0] = packsplit(scf[kc * 2][0],     scf[kc * 2][1],     pl[0]);
            ph[1] = packsplit(scf[kc * 2][2],     scf[kc * 2][3],     pl[1]);
            ph[2] = packsplit(scf[kc * 2 + 1][0], scf[kc * 2 + 1][1], pl[2]);
            ph[3] = packsplit(scf[kc * 2 + 1][2], scf[kc * 2 + 1][3], pl[3]);
#pragma unroll
            for (int dnt = 0; dnt < 4; dnt++) {
                uint32_t vb[4];
                int off = (kc * 16 + lr) * 72 + dnt * 16 + lc;
                ldsm4t(vb, smem_u32(&sVh[off]));
                mma16816(oa[dnt * 2],     ph, vb);
                mma16816(oa[dnt * 2 + 1], ph, vb + 2);
                mma16816(oa[dnt * 2],     pl, vb);
                mma16816(oa[dnt * 2 + 1], pl, vb + 2);
                uint32_t vbl[4];
                ldsm4t(vbl, smem_u32(&sVl[off]));
                mma16816(oa[dnt * 2],     ph, vbl);
                mma16816(oa[dnt * 2 + 1], ph, vbl + 2);
            }
        }
    }

    l0 += __shfl_xor_sync(0xffffffffu, l0, 1);
    l0 += __shfl_xor_sync(0xffffffffu, l0, 2);
    l1 += __shfl_xor_sync(0xffffffffu, l1, 1);
    l1 += __shfl_xor_sync(0xffffffffu, l1, 2);
    float inv0 = 1.f / l0, inv1 = 1.f / l1;

    int r0 = lane >> 2, qc = (lane & 3) * 2;
    size_t orow0 = (qrow0 + wid * 16 + r0) * HID + hoff;
    size_t orow1 = orow0 + (size_t)8 * HID;
#pragma unroll
    for (int j = 0; j < 8; j++) {
        int col = (j >> 1) * 16 + (j & 1) * 8 + qc;
        uint32_t lo0, lo1;
        uint32_t hi0 = packsplit(oa[j][0] * inv0, oa[j][1] * inv0, lo0);
        uint32_t hi1 = packsplit(oa[j][2] * inv1, oa[j][3] * inv1, lo1);
        *(uint32_t*)(Ch + orow0 + col) = hi0;
        *(uint32_t*)(Cl + orow0 + col) = lo0;
        *(uint32_t*)(Ch + orow1 + col) = hi1;
        *(uint32_t*)(Cl + orow1 + col) = lo1;
    }
}

// ---------------- launch ----------------
extern "C" void kernel_launch(void* const* d_in, const int* in_sizes, int n_in,
                              void* d_out, int out_size)
{
    const int*   input_ids = (const int*)d_in[0];
    const int*   type_ids  = (const int*)d_in[1];
    const float* word_emb  = (const float*)d_in[2];
    const float* pos_emb   = (const float*)d_in[3];
    const float* type_emb  = (const float*)d_in[4];
    const float* e_s = (const float*)d_in[5];
    const float* e_b = (const float*)d_in[6];
    const float* wq = (const float*)d_in[7];  const float* bq = (const float*)d_in[8];
    const float* wk = (const float*)d_in[9];  const float* bk = (const float*)d_in[10];
    const float* wv = (const float*)d_in[11]; const float* bv = (const float*)d_in[12];
    const float* wo = (const float*)d_in[13]; const float* bo = (const float*)d_in[14];
    const float* l1s = (const float*)d_in[15]; const float* l1b = (const float*)d_in[16];
    const float* w1 = (const float*)d_in[17]; const float* b1 = (const float*)d_in[18];
    const float* w2 = (const float*)d_in[19]; const float* b2 = (const float*)d_in[20];
    const float* l2s = (const float*)d_in[21]; const float* l2b = (const float*)d_in[22];
    float* out = (float*)d_out;

    float *hp, *tp, *t2p, *t3p;
    __nv_bfloat16 *ahi, *alo, *qkvh, *qkvl, *chp, *clp, *fhp, *flp, *whp, *wlp;
    cudaGetSymbolAddress((void**)&hp,   g_h);
    cudaGetSymbolAddress((void**)&tp,   g_t);
    cudaGetSymbolAddress((void**)&t2p,  g_t2);
    cudaGetSymbolAddress((void**)&t3p,  g_t3);
    cudaGetSymbolAddress((void**)&ahi,  g_ahi);
    cudaGetSymbolAddress((void**)&alo,  g_alo);
    cudaGetSymbolAddress((void**)&qkvh, g_qkvh);
    cudaGetSymbolAddress((void**)&qkvl, g_qkvl);
    cudaGetSymbolAddress((void**)&chp,  g_ch);
    cudaGetSymbolAddress((void**)&clp,  g_cl);
    cudaGetSymbolAddress((void**)&fhp,  g_fh);
    cudaGetSymbolAddress((void**)&flp,  g_fl);
    cudaGetSymbolAddress((void**)&whp,  g_wh);
    cudaGetSymbolAddress((void**)&wlp,  g_wl);

    cudaFuncSetAttribute(hgemm2_kernel<true, false, true>,
                         cudaFuncAttributeMaxDynamicSharedMemorySize, GSMEM);
    cudaFuncSetAttribute(hgemm2_qkv_kernel,
                         cudaFuncAttributeMaxDynamicSharedMemorySize, GSMEM);
    cudaFuncSetAttribute(hgemm2_sk3_kernel,
                         cudaFuncAttributeMaxDynamicSharedMemorySize, GSMEM);
    cudaFuncSetAttribute(fattn_kernel,
                         cudaFuncAttributeMaxDynamicSharedMemorySize, FSMEM);

    // split all weights once per replay
    {
        int n4 = (NLAYER * WSZ_QKVO) / 4;
        dim3 g4((n4 + 255) / 256, 4);
        wsplit4_kernel<<<g4, 256>>>(wq, wk, wv, wo, whp, wlp, n4);
        int n4f = (NLAYER * WSZ_FF) / 4;
        dim3 g2((n4f + 255) / 256, 2);
        wsplit2_kernel<<<g2, 256>>>(w1, w2, whp, wlp, n4f);
    }

    embed_ln_kernel<<<NTOK, 256>>>(input_ids, type_ids, word_emb, pos_emb,
                                   type_emb, e_s, e_b, hp, ahi, alo);

    dim3 gqkv(HID / 128, NTOK / 128, 3);  // (6, 32, 3)
    dim3 gsk (HID / 128, NTOK / 128, 3);  // (6, 32, 3) split-K=3
    dim3 gff (FFD / 128, NTOK / 128);     // (24, 32)
    dim3 gatt(SEQ / 128, BATCH * NHEAD);  // (4, 96)

    const int NHID = NTOK * HID;

    for (int l = 0; l < NLAYER; l++) {
        const __nv_bfloat16* Wqh = whp + OFF_WQ + (size_t)l * WSZ_QKVO;
        const __nv_bfloat16* Wql = wlp + OFF_WQ + (size_t)l * WSZ_QKVO;
        const __nv_bfloat16* Woh = whp + OFF_WO + (size_t)l * WSZ_QKVO;
        const __nv_bfloat16* Wol = wlp + OFF_WO + (size_t)l * WSZ_QKVO;
        const __nv_bfloat16* W1h = whp + OFF_W1 + (size_t)l * WSZ_FF;
        const __nv_bfloat16* W1l = wlp + OFF_W1 + (size_t)l * WSZ_FF;
        const __nv_bfloat16* W2h = whp + OFF_W2 + (size_t)l * WSZ_FF;
        const __nv_bfloat16* W2l = wlp + OFF_W2 + (size_t)l * WSZ_FF;
        const float* Bq = bq + (size_t)l * HID;
        const float* Bk = bk + (size_t)l * HID;
        const float* Bv = bv + (size_t)l * HID;
        const float* Bo = bo + (size_t)l * HID;
        const float* B1 = b1 + (size_t)l * FFD;
        const float* B2 = b2 + (size_t)l * HID;
        const float* L1s = l1s + (size_t)l * HID;
        const float* L1b = l1b + (size_t)l * HID;
        const float* L2s = l2s + (size_t)l * HID;
        const float* L2b = l2b + (size_t)l * HID;

        hgemm2_qkv_kernel<<<gqkv, 256, GSMEM>>>(ahi, alo, Wqh, Wql,
                                                Bq, Bk, Bv, qkvh, qkvl);

        fattn_kernel<<<gatt, 256, FSMEM>>>(
            qkvh, qkvl, qkvh + NHID, qkvl + NHID, qkvh + 2 * NHID, qkvl + 2 * NHID,
            input_ids, chp, clp);

        hgemm2_sk3_kernel<<<gsk, 256, GSMEM>>>(
            chp, clp, Woh, Wol, Bo, hp, tp, t2p, t3p, HID, HID);
        ln3_kernel<<<NTOK, 256>>>(tp, t2p, t3p, L1s, L1b, hp, ahi, alo);

        hgemm2_kernel<true, false, true><<<gff, 256, GSMEM>>>(
            ahi, alo, W1h, W1l, B1, nullptr, nullptr, fhp, flp, FFD, HID);

        hgemm2_sk3_kernel<<<gsk, 256, GSMEM>>>(
            fhp, flp, W2h, W2l, B2, hp, tp, t2p, t3p, HID, FFD);

        if (l == NLAYER - 1)
            ln3_kernel<<<NTOK, 256>>>(tp, t2p, t3p, L2s, L2b, out, nullptr, nullptr);
        else
            ln3_kernel<<<NTOK, 256>>>(tp, t2p, t3p, L2s, L2b, hp, ahi, alo);
    }
}

// round 16
// speedup vs baseline: 1.1304x; 1.0012x over previous
#include <cuda_runtime.h>
#include <cuda_bf16.h>
#include <math.h>
#include <stdint.h>

#define HID    768
#define SEQ    512
#define BATCH  8
#define NHEAD  12
#define DHEAD  64
#define FFD    3072
#define NLAYER 12
#define NTOK   4096   // BATCH*SEQ

// weight split buffer layout (element offsets into g_wh/g_wl)
#define WSZ_QKVO 589824            // 768*768
#define WSZ_FF   2359296           // 768*3072
#define OFF_WQ   0
#define OFF_WK   7077888
#define OFF_WV   14155776
#define OFF_WO   21233664
#define OFF_W1   28311552
#define OFF_W2   56623104
#define WTOT     84934656

// ---------------- scratch (device globals; no allocation allowed) ----------------
__device__ float g_h[NTOK * HID];          // fp32 residual stream
__device__ float g_t[NTOK * HID];          // split-K partial 0 + bias + res
__device__ float g_t2[NTOK * HID];         // split-K partial 1
__device__ float g_t3[NTOK * HID];         // split-K partial 2
__device__ __nv_bfloat16 g_ahi[NTOK * HID], g_alo[NTOK * HID];     // LN out split
__device__ __nv_bfloat16 g_qkvh[3 * NTOK * HID], g_qkvl[3 * NTOK * HID];
__device__ __nv_bfloat16 g_ch[NTOK * HID], g_cl[NTOK * HID];       // attn ctx split
__device__ __nv_bfloat16 g_fh[NTOK * FFD], g_fl[NTOK * FFD];       // gelu out split
__device__ __nv_bfloat16 g_wh[WTOT], g_wl[WTOT];                   // weights split

__device__ __forceinline__ float warpRedSum(float v) {
#pragma unroll
    for (int o = 16; o; o >>= 1) v += __shfl_xor_sync(0xffffffffu, v, o);
    return v;
}
__device__ __forceinline__ uint32_t smem_u32(const void* p) {
    return (uint32_t)__cvta_generic_to_shared(p);
}
__device__ __forceinline__ void ldsm4(uint32_t* r, uint32_t a) {
    asm volatile("ldmatrix.sync.aligned.m8n8.x4.shared.b16 {%0,%1,%2,%3},[%4];"
                 : "=r"(r[0]), "=r"(r[1]), "=r"(r[2]), "=r"(r[3]) : "r"(a));
}
__device__ __forceinline__ void ldsm4t(uint32_t* r, uint32_t a) {
    asm volatile("ldmatrix.sync.aligned.m8n8.x4.trans.shared.b16 {%0,%1,%2,%3},[%4];"
                 : "=r"(r[0]), "=r"(r[1]), "=r"(r[2]), "=r"(r[3]) : "r"(a));
}
__device__ __forceinline__ void mma16816(float* d, const uint32_t* a, const uint32_t* b) {
    asm volatile("mma.sync.aligned.m16n8k16.row.col.f32.bf16.bf16.f32 "
                 "{%0,%1,%2,%3},{%4,%5,%6,%7},{%8,%9},{%0,%1,%2,%3};"
                 : "+f"(d[0]), "+f"(d[1]), "+f"(d[2]), "+f"(d[3])
                 : "r"(a[0]), "r"(a[1]), "r"(a[2]), "r"(a[3]), "r"(b[0]), "r"(b[1]));
}
__device__ __forceinline__ void cp16(uint32_t dst, const void* src) {
    asm volatile("cp.async.cg.shared.global [%0], [%1], 16;" :: "r"(dst), "l"(src));
}
__device__ __forceinline__ void cpcommit() { asm volatile("cp.async.commit_group;"); }
__device__ __forceinline__ void cpwait0()  { asm volatile("cp.async.wait_group 0;"); }
__device__ __forceinline__ void cpwait1()  { asm volatile("cp.async.wait_group 1;"); }

// pack two fp32 into bf16 hi pair (ret) + lo pair (out param)
__device__ __forceinline__ uint32_t packsplit(float a, float b, uint32_t& lo) {
    __nv_bfloat16 ha = __float2bfloat16_rn(a), hb = __float2bfloat16_rn(b);
    __nv_bfloat16 la = __float2bfloat16_rn(a - __bfloat162float(ha));
    __nv_bfloat16 lb = __float2bfloat16_rn(b - __bfloat162float(hb));
    __nv_bfloat162 H(ha, hb), L(la, lb);
    lo = *(uint32_t*)&L;
    return *(uint32_t*)&H;
}

// ---------------- weight split: fp32 -> bf16 hi/lo (merged launches) ----------
__device__ __forceinline__ void wsplit_one(
    const float4* __restrict__ src, uint32_t* __restrict__ dh,
    uint32_t* __restrict__ dl, int i)
{
    float4 v = src[i];
    uint32_t lo0, lo1;
    uint32_t hi0 = packsplit(v.x, v.y, lo0);
    uint32_t hi1 = packsplit(v.z, v.w, lo1);
    dh[2 * i]     = hi0;
    dh[2 * i + 1] = hi1;
    dl[2 * i]     = lo0;
    dl[2 * i + 1] = lo1;
}

__global__ __launch_bounds__(256) void wsplit4_kernel(
    const float* __restrict__ s0, const float* __restrict__ s1,
    const float* __restrict__ s2, const float* __restrict__ s3,
    __nv_bfloat16* __restrict__ dh, __nv_bfloat16* __restrict__ dl, int n4)
{
    int i = blockIdx.x * 256 + threadIdx.x;
    if (i >= n4) return;
    int z = blockIdx.y;
    const float* s = (z == 0) ? s0 : (z == 1) ? s1 : (z == 2) ? s2 : s3;
    size_t off = (size_t)z * OFF_WK;
    wsplit_one((const float4*)s, (uint32_t*)(dh + off), (uint32_t*)(dl + off), i);
}

__global__ __launch_bounds__(256) void wsplit2_kernel(
    const float* __restrict__ s0, const float* __restrict__ s1,
    __nv_bfloat16* __restrict__ dh, __nv_bfloat16* __restrict__ dl, int n4)
{
    int i = blockIdx.x * 256 + threadIdx.x;
    if (i >= n4) return;
    int z = blockIdx.y;
    const float* s = (z == 0) ? s0 : s1;
    size_t off = OFF_W1 + (size_t)z * (OFF_W2 - OFF_W1);
    wsplit_one((const float4*)s, (uint32_t*)(dh + off), (uint32_t*)(dl + off), i);
}

// ---------------- embeddings + layernorm (one block per token) ----------------
__global__ __launch_bounds__(256) void embed_ln_kernel(
    const int* __restrict__ ids, const int* __restrict__ tids,
    const float* __restrict__ we, const float* __restrict__ pe,
    const float* __restrict__ te, const float* __restrict__ sc,
    const float* __restrict__ bi, float* __restrict__ out,
    __nv_bfloat16* __restrict__ oh, __nv_bfloat16* __restrict__ ol)
{
    int row = blockIdx.x;
    int s   = row & (SEQ - 1);
    int tid = threadIdx.x;
    int id  = ids[row];
    int tp  = tids[row];
    const float* wr = we + (size_t)id * HID;
    const float* pr = pe + (size_t)s  * HID;
    const float* tr = te + (size_t)tp * HID;

    float v[3]; float sm = 0.f, sq = 0.f;
#pragma unroll
    for (int u = 0; u < 3; u++) {
        int c = tid + 256 * u;
        float x = wr[c] + pr[c] + tr[c];
        v[u] = x; sm += x; sq += x * x;
    }
    __shared__ float sa[8], sb[8];
    sm = warpRedSum(sm); sq = warpRedSum(sq);
    int lane = tid & 31, w = tid >> 5;
    if (lane == 0) { sa[w] = sm; sb[w] = sq; }
    __syncthreads();
    sm = 0.f; sq = 0.f;
#pragma unroll
    for (int i = 0; i < 8; i++) { sm += sa[i]; sq += sb[i]; }
    float mu  = sm * (1.f / HID);
    float var = fmaxf(sq * (1.f / HID) - mu * mu, 0.f);
    float r   = rsqrtf(var + 1e-12f);
#pragma unroll
    for (int u = 0; u < 3; u++) {
        int c = tid + 256 * u;
        float x = (v[u] - mu) * r * sc[c] + bi[c];
        out[(size_t)row * HID + c] = x;
        __nv_bfloat16 h = __float2bfloat16_rn(x);
        oh[(size_t)row * HID + c] = h;
        ol[(size_t)row * HID + c] = __float2bfloat16_rn(x - __bfloat162float(h));
    }
}

// -------- layernorm over sum of 3 partials (split-K reduce fused in) ----------
__global__ __launch_bounds__(256) void ln3_kernel(
    const float* __restrict__ x, const float* __restrict__ x2,
    const float* __restrict__ x3, const float* __restrict__ sc,
    const float* __restrict__ bi, float* __restrict__ out,
    __nv_bfloat16* __restrict__ oh, __nv_bfloat16* __restrict__ ol)
{
    int row = blockIdx.x;
    int tid = threadIdx.x;
    size_t base = (size_t)row * HID;
    float v[3]; float sm = 0.f, sq = 0.f;
#pragma unroll
    for (int u = 0; u < 3; u++) {
        int c = tid + 256 * u;
        float xv = x[base + c] + x2[base + c] + x3[base + c];
        v[u] = xv; sm += xv; sq += xv * xv;
    }
    __shared__ float sa[8], sb[8];
    sm = warpRedSum(sm); sq = warpRedSum(sq);
    int lane = tid & 31, w = tid >> 5;
    if (lane == 0) { sa[w] = sm; sb[w] = sq; }
    __syncthreads();
    sm = 0.f; sq = 0.f;
#pragma unroll
    for (int i = 0; i < 8; i++) { sm += sa[i]; sq += sb[i]; }
    float mu  = sm * (1.f / HID);
    float var = fmaxf(sq * (1.f / HID) - mu * mu, 0.f);
    float r   = rsqrtf(var + 1e-12f);
#pragma unroll
    for (int u = 0; u < 3; u++) {
        int c = tid + 256 * u;
        float xv = (v[u] - mu) * r * sc[c] + bi[c];
        out[base + c] = xv;
        if (oh) {
            __nv_bfloat16 h = __float2bfloat16_rn(xv);
            oh[base + c] = h;
            ol[base + c] = __float2bfloat16_rn(xv - __bfloat162float(h));
        }
    }
}

// ================= 3-stage pipelined tensor-core GEMM (bf16 hi/lo) =============
#define SAP2 40
#define SBP2 136
#define OFA_L 10240
#define OFB_H 20480
#define OFB_L 29184
#define STAGEB 37888
#define GSMEM  113664    // 3 stages

#define GEMM_MMA_CHUNK(pAh, pAl, pBh, pBl)                                    \
    _Pragma("unroll")                                                         \
    for (int kh = 0; kh < 32; kh += 16) {                                     \
        uint32_t ahf[2][4], alf[2][4];                                        \
        _Pragma("unroll")                                                     \
        for (int mi = 0; mi < 2; mi++) {                                      \
            int off = (wm + mi * 16 + lr) * SAP2 + kh + lc;                   \
            ldsm4(ahf[mi], smem_u32(&(pAh)[off]));                            \
            ldsm4(alf[mi], smem_u32(&(pAl)[off]));                            \
        }                                                                     \
        uint32_t bfh[2][4], bfl[2][4];                                        \
        {                                                                     \
            int off0 = (kh + lr) * SBP2 + wn + lc;                            \
            ldsm4t(bfh[0], smem_u32(&(pBh)[off0]));                           \
            ldsm4t(bfl[0], smem_u32(&(pBl)[off0]));                           \
        }                                                                     \
        _Pragma("unroll")                                                     \
        for (int np = 0; np < 4; np++) {                                      \
            int cur = np & 1, nxt = cur ^ 1;                                  \
            if (np < 3) {                                                     \
                int offn = (kh + lr) * SBP2 + wn + (np + 1) * 16 + lc;        \
                ldsm4t(bfh[nxt], smem_u32(&(pBh)[offn]));                     \
                ldsm4t(bfl[nxt], smem_u32(&(pBl)[offn]));                     \
            }                                                                 \
            _Pragma("unroll")                                                 \
            for (int mi = 0; mi < 2; mi++) {                                  \
                mma16816(acc[mi][np * 2],     ahf[mi], bfh[cur]);             \
                mma16816(acc[mi][np * 2 + 1], ahf[mi], bfh[cur] + 2);         \
            }                                                                 \
            _Pragma("unroll")                                                 \
            for (int mi = 0; mi < 2; mi++) {                                  \
                mma16816(acc[mi][np * 2],     alf[mi], bfh[cur]);             \
                mma16816(acc[mi][np * 2 + 1], alf[mi], bfh[cur] + 2);         \
            }                                                                 \
            _Pragma("unroll")                                                 \
            for (int mi = 0; mi < 2; mi++) {                                  \
                mma16816(acc[mi][np * 2],     ahf[mi], bfl[cur]);             \
                mma16816(acc[mi][np * 2 + 1], ahf[mi], bfl[cur] + 2);         \
            }                                                                 \
        }                                                                     \
    }

template <bool GELU, bool HASRES, bool SPLITOUT>
__device__ __forceinline__ void gemm2_body(
    const __nv_bfloat16* __restrict__ Ah, const __nv_bfloat16* __restrict__ Al,
    const __nv_bfloat16* __restrict__ Wh, const __nv_bfloat16* __restrict__ Wl,
    const float* __restrict__ bias, const float* __restrict__ res,
    float* __restrict__ C, __nv_bfloat16* __restrict__ Ch, __nv_bfloat16* __restrict__ Cl,
    int N, int K, int row0, int col0)
{
    extern __shared__ char dsm[];
    uint32_t sbase = smem_u32(dsm);
    int tid = threadIdx.x, lane = tid & 31, wid = tid >> 5;
    int wm = (wid & 3) * 32, wn = (wid >> 2) * 64;
    int lr = lane & 15, lc = (lane >> 4) * 8;

    int arow = tid >> 1, ac = (tid & 1) * 16;
    int brow = tid >> 3, bc = (tid & 7) * 16;
    const __nv_bfloat16* gAh = Ah + (size_t)(row0 + arow) * K + ac;
    const __nv_bfloat16* gAl = Al + (size_t)(row0 + arow) * K + ac;
    const __nv_bfloat16* gWh = Wh + (size_t)brow * N + col0 + bc;
    const __nv_bfloat16* gWl = Wl + (size_t)brow * N + col0 + bc;
    uint32_t sa = sbase + (arow * SAP2 + ac) * 2;
    uint32_t sb = sbase + OFB_H + (brow * SBP2 + bc) * 2;

    float acc[2][8][4] = {};

    auto load = [&](int stage, int k0) {
        uint32_t s0 = (uint32_t)stage * STAGEB;
        cp16(sa + s0,              gAh + k0);
        cp16(sa + s0 + 16,         gAh + k0 + 8);
        cp16(sa + s0 + OFA_L,      gAl + k0);
        cp16(sa + s0 + OFA_L + 16, gAl + k0 + 8);
        const __nv_bfloat16* wh = gWh + (size_t)k0 * N;
        const __nv_bfloat16* wl = gWl + (size_t)k0 * N;
        cp16(sb + s0,                       wh);
        cp16(sb + s0 + 16,                  wh + 8);
        cp16(sb + s0 + (OFB_L - OFB_H),      wl);
        cp16(sb + s0 + (OFB_L - OFB_H) + 16, wl + 8);
    };

    int NK = K / 32;
    load(0, 0); cpcommit();
    load(1, 32); cpcommit();

    for (int kt = 0; kt < NK; kt++) {
        if (kt + 1 < NK) cpwait1(); else cpwait0();
        __syncthreads();
        if (kt + 2 < NK) {
            int s2 = (kt + 2) - ((kt + 2) / 3) * 3;
            load(s2, (kt + 2) * 32); cpcommit();
        }
        const char* st = dsm + (kt - (kt / 3) * 3) * STAGEB;
        const __nv_bfloat16* pAh = (const __nv_bfloat16*)st;
        const __nv_bfloat16* pAl = (const __nv_bfloat16*)(st + OFA_L);
        const __nv_bfloat16* pBh = (const __nv_bfloat16*)(st + OFB_H);
        const __nv_bfloat16* pBl = (const __nv_bfloat16*)(st + OFB_L);
        GEMM_MMA_CHUNK(pAh, pAl, pBh, pBl)
    }

    int gid = lane >> 2, qc = (lane & 3) * 2;
#pragma unroll
    for (int mi = 0; mi < 2; mi++)
#pragma unroll
    for (int half = 0; half < 2; half++) {
        int r = row0 + wm + mi * 16 + gid + half * 8;
#pragma unroll
        for (int n8 = 0; n8 < 8; n8++) {
            int c = col0 + wn + n8 * 8 + qc;
            float x0 = acc[mi][n8][half * 2 + 0] + bias[c];
            float x1 = acc[mi][n8][half * 2 + 1] + bias[c + 1];
            if (HASRES) {
                x0 += res[(size_t)r * N + c];
                x1 += res[(size_t)r * N + c + 1];
            }
            if (GELU) {
                x0 = 0.5f * x0 * (1.f + erff(x0 * 0.70710678118654752f));
                x1 = 0.5f * x1 * (1.f + erff(x1 * 0.70710678118654752f));
            }
            if (SPLITOUT) {
                uint32_t lo, hi = packsplit(x0, x1, lo);
                *(uint32_t*)(Ch + (size_t)r * N + c) = hi;
                *(uint32_t*)(Cl + (size_t)r * N + c) = lo;
            } else {
                *(float2*)(C + (size_t)r * N + c) = make_float2(x0, x1);
            }
        }
    }
}

template <bool GELU, bool HASRES, bool SPLITOUT>
__global__ __launch_bounds__(256, 2) void hgemm2_kernel(
    const __nv_bfloat16* __restrict__ Ah, const __nv_bfloat16* __restrict__ Al,
    const __nv_bfloat16* __restrict__ Wh, const __nv_bfloat16* __restrict__ Wl,
    const float* __restrict__ bias, const float* __restrict__ res,
    float* __restrict__ C, __nv_bfloat16* __restrict__ Ch, __nv_bfloat16* __restrict__ Cl,
    int N, int K)
{
    gemm2_body<GELU, HASRES, SPLITOUT>(Ah, Al, Wh, Wl, bias, res, C, Ch, Cl,
                                       N, K, blockIdx.y * 128, blockIdx.x * 128);
}

__global__ __launch_bounds__(256, 2) void hgemm2_qkv_kernel(
    const __nv_bfloat16* __restrict__ Ah, const __nv_bfloat16* __restrict__ Al,
    const __nv_bfloat16* __restrict__ Whb, const __nv_bfloat16* __restrict__ Wlb,
    const float* __restrict__ b0, const float* __restrict__ b1, const float* __restrict__ b2,
    __nv_bfloat16* __restrict__ Chb, __nv_bfloat16* __restrict__ Clb)
{
    int z = blockIdx.z;
    const __nv_bfloat16* Wh = Whb + (size_t)z * OFF_WK;
    const __nv_bfloat16* Wl = Wlb + (size_t)z * OFF_WK;
    const float* bias = (z == 0) ? b0 : (z == 1) ? b1 : b2;
    __nv_bfloat16* Ch = Chb + (size_t)z * NTOK * HID;
    __nv_bfloat16* Cl = Clb + (size_t)z * NTOK * HID;
    gemm2_body<false, false, true>(Ah, Al, Wh, Wl, bias, nullptr, nullptr, Ch, Cl,
                                   HID, HID, blockIdx.y * 128, blockIdx.x * 128);
}

// ---- split-K=3 GEMM: z=0 stores partial+bias+res to C0; z=1/2 raw to C1/C2 ---
__device__ __forceinline__ void gemm2_sk_body(
    const __nv_bfloat16* __restrict__ Ah, const __nv_bfloat16* __restrict__ Al,
    const __nv_bfloat16* __restrict__ Wh, const __nv_bfloat16* __restrict__ Wl,
    const float* __restrict__ bias, const float* __restrict__ res,
    float* __restrict__ Cout, bool first,
    int N, int K, int Kp, int kbase, int row0, int col0)
{
    extern __shared__ char dsm[];
    uint32_t sbase = smem_u32(dsm);
    int tid = threadIdx.x, lane = tid & 31, wid = tid >> 5;
    int wm = (wid & 3) * 32, wn = (wid >> 2) * 64;
    int lr = lane & 15, lc = (lane >> 4) * 8;

    int arow = tid >> 1, ac = (tid & 1) * 16;
    int brow = tid >> 3, bc = (tid & 7) * 16;
    const __nv_bfloat16* gAh = Ah + (size_t)(row0 + arow) * K + kbase + ac;
    const __nv_bfloat16* gAl = Al + (size_t)(row0 + arow) * K + kbase + ac;
    const __nv_bfloat16* gWh = Wh + (size_t)(kbase + brow) * N + col0 + bc;
    const __nv_bfloat16* gWl = Wl + (size_t)(kbase + brow) * N + col0 + bc;
    uint32_t sa = sbase + (arow * SAP2 + ac) * 2;
    uint32_t sb = sbase + OFB_H + (brow * SBP2 + bc) * 2;

    float acc[2][8][4] = {};

    auto load = [&](int stage, int k0) {
        uint32_t s0 = (uint32_t)stage * STAGEB;
        cp16(sa + s0,              gAh + k0);
        cp16(sa + s0 + 16,         gAh + k0 + 8);
        cp16(sa + s0 + OFA_L,      gAl + k0);
        cp16(sa + s0 + OFA_L + 16, gAl + k0 + 8);
        const __nv_bfloat16* wh = gWh + (size_t)k0 * N;
        const __nv_bfloat16* wl = gWl + (size_t)k0 * N;
        cp16(sb + s0,                       wh);
        cp16(sb + s0 + 16,                  wh + 8);
        cp16(sb + s0 + (OFB_L - OFB_H),      wl);
        cp16(sb + s0 + (OFB_L - OFB_H) + 16, wl + 8);
    };

    int NK = Kp / 32;
    load(0, 0); cpcommit();
    load(1, 32); cpcommit();

    for (int kt = 0; kt < NK; kt++) {
        if (kt + 1 < NK) cpwait1(); else cpwait0();
        __syncthreads();
        if (kt + 2 < NK) {
            int s2 = (kt + 2) - ((kt + 2) / 3) * 3;
            load(s2, (kt + 2) * 32); cpcommit();
        }
        const char* st = dsm + (kt - (kt / 3) * 3) * STAGEB;
        const __nv_bfloat16* pAh = (const __nv_bfloat16*)st;
        const __nv_bfloat16* pAl = (const __nv_bfloat16*)(st + OFA_L);
        const __nv_bfloat16* pBh = (const __nv_bfloat16*)(st + OFB_H);
        const __nv_bfloat16* pBl = (const __nv_bfloat16*)(st + OFB_L);
        GEMM_MMA_CHUNK(pAh, pAl, pBh, pBl)
    }

    int gid = lane >> 2, qc = (lane & 3) * 2;
#pragma unroll
    for (int mi = 0; mi < 2; mi++)
#pragma unroll
    for (int half = 0; half < 2; half++) {
        int r = row0 + wm + mi * 16 + gid + half * 8;
#pragma unroll
        for (int n8 = 0; n8 < 8; n8++) {
            int c = col0 + wn + n8 * 8 + qc;
            float x0 = acc[mi][n8][half * 2 + 0];
            float x1 = acc[mi][n8][half * 2 + 1];
            if (first) {
                x0 += bias[c]     + res[(size_t)r * N + c];
                x1 += bias[c + 1] + res[(size_t)r * N + c + 1];
            }
            *(float2*)(Cout + (size_t)r * N + c) = make_float2(x0, x1);
        }
    }
}

__global__ __launch_bounds__(256, 2) void hgemm2_sk3_kernel(
    const __nv_bfloat16* __restrict__ Ah, const __nv_bfloat16* __restrict__ Al,
    const __nv_bfloat16* __restrict__ Wh, const __nv_bfloat16* __restrict__ Wl,
    const float* __restrict__ bias, const float* __restrict__ res,
    float* __restrict__ C0, float* __restrict__ C1, float* __restrict__ C2,
    int N, int K)
{
    int z = blockIdx.z;
    int Kp = K / 3;
    float* Cout = (z == 0) ? C0 : (z == 1) ? C1 : C2;
    gemm2_sk_body(Ah, Al, Wh, Wl, bias, res, Cout, z == 0,
                  N, K, Kp, z * Kp, blockIdx.y * 128, blockIdx.x * 128);
}

// ================= flash attention (bf16 hi/lo MMA, online softmax) ============
// cp.async double-buffered K/V tiles: prefetch kt+1 while computing kt.
// smem: Q 2x18432 | K/V 2 buffers x (4 x 9216) | mask 2048 = 112640 B
#define OQL 18432
#define OKV 36864
#define KVSTRIDE 36864
#define KV_KL 9216
#define KV_VH 18432
#define KV_VL 27648
#define OMS 110592
#define FSMEM 112640

__global__ __launch_bounds__(256, 2) void fattn_kernel(
    const __nv_bfloat16* __restrict__ Qh, const __nv_bfloat16* __restrict__ Ql,
    const __nv_bfloat16* __restrict__ Kh, const __nv_bfloat16* __restrict__ Kl,
    const __nv_bfloat16* __restrict__ Vh, const __nv_bfloat16* __restrict__ Vl,
    const int* __restrict__ ids,
    __nv_bfloat16* __restrict__ Ch, __nv_bfloat16* __restrict__ Cl)
{
    extern __shared__ char dsm[];
    __nv_bfloat16* sQh = (__nv_bfloat16*)dsm;
    __nv_bfloat16* sQl = (__nv_bfloat16*)(dsm + OQL);
    float* sMask = (float*)(dsm + OMS);
    uint32_t kvbase = smem_u32(dsm + OKV);

    int tid = threadIdx.x, lane = tid & 31, wid = tid >> 5;
    int bh = blockIdx.y, b = bh / NHEAD, h = bh % NHEAD;
    int q0 = blockIdx.x * 128;
    size_t hoff = (size_t)h * DHEAD;
    size_t qrow0 = (size_t)(b * SEQ + q0);
    int lr = lane & 15, lc = (lane >> 4) * 8;

    for (int j = tid; j < SEQ; j += 256)
        sMask[j] = (ids[b * SEQ + j] == 0) ? -10000.f : 0.f;

    // K/V prefetch via cp.async: each thread loads 2x16B per tensor
    int kvr = tid >> 2, kvc = (tid & 3) * 32;   // row 0..63, byte col 0,32,64,96
    uint32_t kvdst = kvr * 144 + kvc;
    auto loadKV = [&](int kt, int buf) {
        size_t grow = ((size_t)(b * SEQ + kt * 64 + kvr) * HID + hoff) * 2 + kvc;
        uint32_t d = kvbase + (uint32_t)buf * KVSTRIDE + kvdst;
        cp16(d,              (const char*)Kh + grow);
        cp16(d + 16,         (const char*)Kh + grow + 16);
        cp16(d + KV_KL,      (const char*)Kl + grow);
        cp16(d + KV_KL + 16, (const char*)Kl + grow + 16);
        cp16(d + KV_VH,      (const char*)Vh + grow);
        cp16(d + KV_VH + 16, (const char*)Vh + grow + 16);
        cp16(d + KV_VL,      (const char*)Vl + grow);
        cp16(d + KV_VL + 16, (const char*)Vl + grow + 16);
    };

    loadKV(0, 0); cpcommit();

    {   // load Q tile (128 x 64) hi/lo into smem (stride 72 elems = 144B rows)
        int r = tid >> 1, cs = (tid & 1) * 4;
        const uint4* srch = (const uint4*)(Qh + (qrow0 + r) * HID + hoff);
        const uint4* srcl = (const uint4*)(Ql + (qrow0 + r) * HID + hoff);
        uint4* dsth = (uint4*)((char*)sQh + r * 144);
        uint4* dstl = (uint4*)((char*)sQl + r * 144);
#pragma unroll
        for (int j = 0; j < 4; j++) { dsth[cs + j] = srch[cs + j]; dstl[cs + j] = srcl[cs + j]; }
    }
    __syncthreads();

    uint32_t qfh[4][4], qfl[4][4];
#pragma unroll
    for (int kc = 0; kc < 4; kc++) {
        ldsm4(qfh[kc], smem_u32(&sQh[(wid * 16 + lr) * 72 + kc * 16 + lc]));
        ldsm4(qfl[kc], smem_u32(&sQl[(wid * 16 + lr) * 72 + kc * 16 + lc]));
    }

    float m0 = -1e30f, m1 = -1e30f, l0 = 0.f, l1 = 0.f;
    float oa[8][4] = {};

    for (int kt = 0; kt < 8; kt++) {
        cpwait0();
        __syncthreads();           // buf[kt&1] ready; prior compute done
        if (kt < 7) { loadKV(kt + 1, (kt + 1) & 1); cpcommit(); }

        const char* kb = dsm + OKV + (kt & 1) * KVSTRIDE;
        const __nv_bfloat16* sKh = (const __nv_bfloat16*)kb;
        const __nv_bfloat16* sKl = (const __nv_bfloat16*)(kb + KV_KL);
        const __nv_bfloat16* sVh = (const __nv_bfloat16*)(kb + KV_VH);
        const __nv_bfloat16* sVl = (const __nv_bfloat16*)(kb + KV_VL);

        float scf[8][4] = {};
#pragma unroll
        for (int kc = 0; kc < 4; kc++) {
#pragma unroll
            for (int nt2 = 0; nt2 < 4; nt2++) {
                uint32_t kb4[4];
                int off = (nt2 * 16 + lr) * 72 + kc * 16 + lc;
                ldsm4(kb4, smem_u32(&sKh[off]));
                uint32_t b0[2] = {kb4[0], kb4[2]}, b1[2] = {kb4[1], kb4[3]};
                mma16816(scf[nt2 * 2],     qfh[kc], b0);
                mma16816(scf[nt2 * 2 + 1], qfh[kc], b1);
                mma16816(scf[nt2 * 2],     qfl[kc], b0);
                mma16816(scf[nt2 * 2 + 1], qfl[kc], b1);
                uint32_t kbl[4];
                ldsm4(kbl, smem_u32(&sKl[off]));
                uint32_t b0l[2] = {kbl[0], kbl[2]}, b1l[2] = {kbl[1], kbl[3]};
                mma16816(scf[nt2 * 2],     qfh[kc], b0l);
                mma16816(scf[nt2 * 2 + 1], qfh[kc], b1l);
            }
        }
        float tmax0 = -1e30f, tmax1 = -1e30f;
#pragma unroll
        for (int nt = 0; nt < 8; nt++) {
            int kbk = kt * 64 + (nt >> 1) * 16 + (nt & 1) * 8 + 2 * (lane & 3);
            float mb0 = sMask[kbk], mb1 = sMask[kbk + 1];
            scf[nt][0] = scf[nt][0] * 0.125f + mb0;
            scf[nt][1] = scf[nt][1] * 0.125f + mb1;
            scf[nt][2] = scf[nt][2] * 0.125f + mb0;
            scf[nt][3] = scf[nt][3] * 0.125f + mb1;
            tmax0 = fmaxf(tmax0, fmaxf(scf[nt][0], scf[nt][1]));
            tmax1 = fmaxf(tmax1, fmaxf(scf[nt][2], scf[nt][3]));
        }
        tmax0 = fmaxf(tmax0, __shfl_xor_sync(0xffffffffu, tmax0, 1));
        tmax0 = fmaxf(tmax0, __shfl_xor_sync(0xffffffffu, tmax0, 2));
        tmax1 = fmaxf(tmax1, __shfl_xor_sync(0xffffffffu, tmax1, 1));
        tmax1 = fmaxf(tmax1, __shfl_xor_sync(0xffffffffu, tmax1, 2));
        float mn0 = fmaxf(m0, tmax0), mn1 = fmaxf(m1, tmax1);
        float sc0 = __expf(m0 - mn0), sc1 = __expf(m1 - mn1);
        m0 = mn0; m1 = mn1;
        float ls0 = 0.f, ls1 = 0.f;
#pragma unroll
        for (int nt = 0; nt < 8; nt++) {
            scf[nt][0] = __expf(scf[nt][0] - m0);
            scf[nt][1] = __expf(scf[nt][1] - m0);
            scf[nt][2] = __expf(scf[nt][2] - m1);
            scf[nt][3] = __expf(scf[nt][3] - m1);
            ls0 += scf[nt][0] + scf[nt][1];
            ls1 += scf[nt][2] + scf[nt][3];
        }
        l0 = l0 * sc0 + ls0; l1 = l1 * sc1 + ls1;
#pragma unroll
        for (int j = 0; j < 8; j++) {
            oa[j][0] *= sc0; oa[j][1] *= sc0;
            oa[j][2] *= sc1; oa[j][3] *= sc1;
        }
#pragma unroll
        for (int kc = 0; kc < 4; kc++) {
            uint32_t ph[4], pl[4];
            ph[0] = packsplit(scf[kc * 2][0],     scf[kc * 2][1],     pl[0]);
            ph[1] = packsplit(scf[kc * 2][2],     scf[kc * 2][3],     pl[1]);
            ph[2] = packsplit(scf[kc * 2 + 1][0], scf[kc * 2 + 1][1], pl[2]);
            ph[3] = packsplit(scf[kc * 2 + 1][2], scf[kc * 2 + 1][3], pl[3]);
#pragma unroll
            for (int dnt = 0; dnt < 4; dnt++) {
                uint32_t vb[4];
                int off = (kc * 16 + lr) * 72 + dnt * 16 + lc;
                ldsm4t(vb, smem_u32(&sVh[off]));
                mma16816(oa[dnt * 2],     ph, vb);
                mma16816(oa[dnt * 2 + 1], ph, vb + 2);
                mma16816(oa[dnt * 2],     pl, vb);
                mma16816(oa[dnt * 2 + 1], pl, vb + 2);
                uint32_t vbl[4];
                ldsm4t(vbl, smem_u32(&sVl[off]));
                mma16816(oa[dnt * 2],     ph, vbl);
                mma16816(oa[dnt * 2 + 1], ph, vbl + 2);
            }
        }
        __syncthreads();           // all warps done with buf[kt&1] before next overwrite
    }

    l0 += __shfl_xor_sync(0xffffffffu, l0, 1);
    l0 += __shfl_xor_sync(0xffffffffu, l0, 2);
    l1 += __shfl_xor_sync(0xffffffffu, l1, 1);
    l1 += __shfl_xor_sync(0xffffffffu, l1, 2);
    float inv0 = 1.f / l0, inv1 = 1.f / l1;

    int r0 = lane >> 2, qc = (lane & 3) * 2;
    size_t orow0 = (qrow0 + wid * 16 + r0) * HID + hoff;
    size_t orow1 = orow0 + (size_t)8 * HID;
#pragma unroll
    for (int j = 0; j < 8; j++) {
        int col = (j >> 1) * 16 + (j & 1) * 8 + qc;
        uint32_t lo0, lo1;
        uint32_t hi0 = packsplit(oa[j][0] * inv0, oa[j][1] * inv0, lo0);
        uint32_t hi1 = packsplit(oa[j][2] * inv1, oa[j][3] * inv1, lo1);
        *(uint32_t*)(Ch + orow0 + col) = hi0;
        *(uint32_t*)(Cl + orow0 + col) = lo0;
        *(uint32_t*)(Ch + orow1 + col) = hi1;
        *(uint32_t*)(Cl + orow1 + col) = lo1;
    }
}

// ---------------- launch ----------------
extern "C" void kernel_launch(void* const* d_in, const int* in_sizes, int n_in,
                              void* d_out, int out_size)
{
    const int*   input_ids = (const int*)d_in[0];
    const int*   type_ids  = (const int*)d_in[1];
    const float* word_emb  = (const float*)d_in[2];
    const float* pos_emb   = (const float*)d_in[3];
    const float* type_emb  = (const float*)d_in[4];
    const float* e_s = (const float*)d_in[5];
    const float* e_b = (const float*)d_in[6];
    const float* wq = (const float*)d_in[7];  const float* bq = (const float*)d_in[8];
    const float* wk = (const float*)d_in[9];  const float* bk = (const float*)d_in[10];
    const float* wv = (const float*)d_in[11]; const float* bv = (const float*)d_in[12];
    const float* wo = (const float*)d_in[13]; const float* bo = (const float*)d_in[14];
    const float* l1s = (const float*)d_in[15]; const float* l1b = (const float*)d_in[16];
    const float* w1 = (const float*)d_in[17]; const float* b1 = (const float*)d_in[18];
    const float* w2 = (const float*)d_in[19]; const float* b2 = (const float*)d_in[20];
    const float* l2s = (const float*)d_in[21]; const float* l2b = (const float*)d_in[22];
    float* out = (float*)d_out;

    float *hp, *tp, *t2p, *t3p;
    __nv_bfloat16 *ahi, *alo, *qkvh, *qkvl, *chp, *clp, *fhp, *flp, *whp, *wlp;
    cudaGetSymbolAddress((void**)&hp,   g_h);
    cudaGetSymbolAddress((void**)&tp,   g_t);
    cudaGetSymbolAddress((void**)&t2p,  g_t2);
    cudaGetSymbolAddress((void**)&t3p,  g_t3);
    cudaGetSymbolAddress((void**)&ahi,  g_ahi);
    cudaGetSymbolAddress((void**)&alo,  g_alo);
    cudaGetSymbolAddress((void**)&qkvh, g_qkvh);
    cudaGetSymbolAddress((void**)&qkvl, g_qkvl);
    cudaGetSymbolAddress((void**)&chp,  g_ch);
    cudaGetSymbolAddress((void**)&clp,  g_cl);
    cudaGetSymbolAddress((void**)&fhp,  g_fh);
    cudaGetSymbolAddress((void**)&flp,  g_fl);
    cudaGetSymbolAddress((void**)&whp,  g_wh);
    cudaGetSymbolAddress((void**)&wlp,  g_wl);

    cudaFuncSetAttribute(hgemm2_kernel<true, false, true>,
                         cudaFuncAttributeMaxDynamicSharedMemorySize, GSMEM);
    cudaFuncSetAttribute(hgemm2_qkv_kernel,
                         cudaFuncAttributeMaxDynamicSharedMemorySize, GSMEM);
    cudaFuncSetAttribute(hgemm2_sk3_kernel,
                         cudaFuncAttributeMaxDynamicSharedMemorySize, GSMEM);
    cudaFuncSetAttribute(fattn_kernel,
                         cudaFuncAttributeMaxDynamicSharedMemorySize, FSMEM);

    // split all weights once per replay
    {
        int n4 = (NLAYER * WSZ_QKVO) / 4;
        dim3 g4((n4 + 255) / 256, 4);
        wsplit4_kernel<<<g4, 256>>>(wq, wk, wv, wo, whp, wlp, n4);
        int n4f = (NLAYER * WSZ_FF) / 4;
        dim3 g2((n4f + 255) / 256, 2);
        wsplit2_kernel<<<g2, 256>>>(w1, w2, whp, wlp, n4f);
    }

    embed_ln_kernel<<<NTOK, 256>>>(input_ids, type_ids, word_emb, pos_emb,
                                   type_emb, e_s, e_b, hp, ahi, alo);

    dim3 gqkv(HID / 128, NTOK / 128, 3);  // (6, 32, 3)
    dim3 gsk (HID / 128, NTOK / 128, 3);  // (6, 32, 3) split-K=3
    dim3 gff (FFD / 128, NTOK / 128);     // (24, 32)
    dim3 gatt(SEQ / 128, BATCH * NHEAD);  // (4, 96)

    const int NHID = NTOK * HID;

    for (int l = 0; l < NLAYER; l++) {
        const __nv_bfloat16* Wqh = whp + OFF_WQ + (size_t)l * WSZ_QKVO;
        const __nv_bfloat16* Wql = wlp + OFF_WQ + (size_t)l * WSZ_QKVO;
        const __nv_bfloat16* Woh = whp + OFF_WO + (size_t)l * WSZ_QKVO;
        const __nv_bfloat16* Wol = wlp + OFF_WO + (size_t)l * WSZ_QKVO;
        const __nv_bfloat16* W1h = whp + OFF_W1 + (size_t)l * WSZ_FF;
        const __nv_bfloat16* W1l = wlp + OFF_W1 + (size_t)l * WSZ_FF;
        const __nv_bfloat16* W2h = whp + OFF_W2 + (size_t)l * WSZ_FF;
        const __nv_bfloat16* W2l = wlp + OFF_W2 + (size_t)l * WSZ_FF;
        const float* Bq = bq + (size_t)l * HID;
        const float* Bk = bk + (size_t)l * HID;
        const float* Bv = bv + (size_t)l * HID;
        const float* Bo = bo + (size_t)l * HID;
        const float* B1 = b1 + (size_t)l * FFD;
        const float* B2 = b2 + (size_t)l * HID;
        const float* L1s = l1s + (size_t)l * HID;
        const float* L1b = l1b + (size_t)l * HID;
        const float* L2s = l2s + (size_t)l * HID;
        const float* L2b = l2b + (size_t)l * HID;

        hgemm2_qkv_kernel<<<gqkv, 256, GSMEM>>>(ahi, alo, Wqh, Wql,
                                                Bq, Bk, Bv, qkvh, qkvl);

        fattn_kernel<<<gatt, 256, FSMEM>>>(
            qkvh, qkvl, qkvh + NHID, qkvl + NHID, qkvh + 2 * NHID, qkvl + 2 * NHID,
            input_ids, chp, clp);

        hgemm2_sk3_kernel<<<gsk, 256, GSMEM>>>(
            chp, clp, Woh, Wol, Bo, hp, tp, t2p, t3p, HID, HID);
        ln3_kernel<<<NTOK, 256>>>(tp, t2p, t3p, L1s, L1b, hp, ahi, alo);

        hgemm2_kernel<true, false, true><<<gff, 256, GSMEM>>>(
            ahi, alo, W1h, W1l, B1, nullptr, nullptr, fhp, flp, FFD, HID);

        hgemm2_sk3_kernel<<<gsk, 256, GSMEM>>>(
            fhp, flp, W2h, W2l, B2, hp, tp, t2p, t3p, HID, FFD);

        if (l == NLAYER - 1)
            ln3_kernel<<<NTOK, 256>>>(tp, t2p, t3p, L2s, L2b, out, nullptr, nullptr);
        else
            ln3_kernel<<<NTOK, 256>>>(tp, t2p, t3p, L2s, L2b, hp, ahi, alo);
    }
}